// round 8
// baseline (speedup 1.0000x reference)
#include <cuda_runtime.h>
#include <cuda_fp16.h>

#define NN 100000
#define NE 1600000
#define FD 128
#define NH 512
#define NC 64
#define SCAN_BLOCKS 98   // ceil(100000/1024)

// ---------------- device scratch ----------------
__device__ int    g_deg[NN + 1];
__device__ int    g_incl[NN];
__device__ int    g_blktot[128];
__device__ int    g_rowptr[NN + 1];
__device__ int    g_cursor[NN];
__device__ int2   g_edge[NE];       // (src, wgt bits) interleaved
__device__ __half g_fh0[NN * FD];
__device__ __half g_fh1[NN * FD];
__device__ __half g_hh[NN * NH];
__device__ __half g_w1h[NH * FD];   // fc1_w as fp16
__device__ __half g_w2h[NC * NH];   // fc2_w as fp16
__device__ float  g_colsum[NH];
__device__ float  g_colsq[NH];

// ---------------- mma / ldmatrix helpers ----------------
__device__ __forceinline__ void mma_f16(float* c, const unsigned* a, const unsigned* b) {
    asm volatile(
        "mma.sync.aligned.m16n8k16.row.col.f32.f16.f16.f32 "
        "{%0,%1,%2,%3}, {%4,%5,%6,%7}, {%8,%9}, {%0,%1,%2,%3};"
        : "+f"(c[0]), "+f"(c[1]), "+f"(c[2]), "+f"(c[3])
        : "r"(a[0]), "r"(a[1]), "r"(a[2]), "r"(a[3]), "r"(b[0]), "r"(b[1]));
}

__device__ __forceinline__ void ldsm_x4(unsigned* r, unsigned addr) {
    asm volatile("ldmatrix.sync.aligned.m8n8.x4.shared.b16 {%0,%1,%2,%3}, [%4];"
                 : "=r"(r[0]), "=r"(r[1]), "=r"(r[2]), "=r"(r[3]) : "r"(addr));
}

__device__ __forceinline__ void ldsm_x2(unsigned* r, unsigned addr) {
    asm volatile("ldmatrix.sync.aligned.m8n8.x2.shared.b16 {%0,%1}, [%2];"
                 : "=r"(r[0]), "=r"(r[1]) : "r"(addr));
}

// ---------------- cvt + zero ----------------
__global__ void k_cvt(const float* __restrict__ feat,
                      const float* __restrict__ w1,
                      const float* __restrict__ w2) {
    int i = blockIdx.x * blockDim.x + threadIdx.x;
    if (i < NN * FD / 2) {
        float2 v = ((const float2*)feat)[i];
        ((__half2*)g_fh1)[i] = __float22half2_rn(v);
    }
    if (i < NH * FD / 2) {
        float2 v = ((const float2*)w1)[i];
        ((__half2*)g_w1h)[i] = __float22half2_rn(v);
    }
    if (i < NC * NH / 2) {
        float2 v = ((const float2*)w2)[i];
        ((__half2*)g_w2h)[i] = __float22half2_rn(v);
    }
    if (i < NN + 1) g_deg[i] = 0;
    if (i < NH) { g_colsum[i] = 0.f; g_colsq[i] = 0.f; }
}

// ---------------- CSR build ----------------
__global__ void k_hist(const int* __restrict__ dst) {
    int e = blockIdx.x * blockDim.x + threadIdx.x;
    if (e < NE) atomicAdd(&g_deg[dst[e]], 1);
}

__global__ void k_scan1() {
    __shared__ int sh[1024];
    int i = blockIdx.x * 1024 + threadIdx.x;
    int v = (i < NN) ? g_deg[i] : 0;
    sh[threadIdx.x] = v;
    __syncthreads();
    #pragma unroll
    for (int off = 1; off < 1024; off <<= 1) {
        int t = (threadIdx.x >= off) ? sh[threadIdx.x - off] : 0;
        __syncthreads();
        sh[threadIdx.x] += t;
        __syncthreads();
    }
    if (i < NN) g_incl[i] = sh[threadIdx.x];
    if (threadIdx.x == 1023) g_blktot[blockIdx.x] = sh[1023];
}

__global__ void k_scan23() {
    __shared__ int sh[128];
    if (threadIdx.x < 128)
        sh[threadIdx.x] = (threadIdx.x < SCAN_BLOCKS) ? g_blktot[threadIdx.x] : 0;
    __syncthreads();
    #pragma unroll
    for (int off = 1; off < 128; off <<= 1) {
        int t = 0;
        if (threadIdx.x < 128 && threadIdx.x >= off) t = sh[threadIdx.x - off];
        __syncthreads();
        if (threadIdx.x < 128) sh[threadIdx.x] += t;
        __syncthreads();
    }
    int base = (blockIdx.x == 0) ? 0 : sh[blockIdx.x - 1];
    int i = blockIdx.x * 1024 + threadIdx.x;
    if (i < NN) {
        int excl = g_incl[i] - g_deg[i] + base;
        g_rowptr[i] = excl;
        g_cursor[i] = excl;
        if (i == NN - 1) g_rowptr[NN] = g_incl[i] + base;
    }
}

__global__ void k_scatter(const int* __restrict__ src, const int* __restrict__ dst,
                          const float* __restrict__ nrm) {
    int e = blockIdx.x * blockDim.x + threadIdx.x;
    if (e < NE) {
        int d = dst[e];
        int pos = atomicAdd(&g_cursor[d], 1);
        g_edge[pos] = make_int2(src[e], __float_as_int(nrm[e]));
    }
}

// ---------------- K-hop propagation: warp per dst, fp16 rows, fp32 accum (unroll-2) ----------------
__global__ void k_prop(int par) {
    int gt = blockIdx.x * blockDim.x + threadIdx.x;
    int node = gt >> 5;
    int lane = gt & 31;
    if (node >= NN) return;
    const uint2* in2  = (const uint2*)(par ? g_fh0 : g_fh1);
    uint2*       out2 = (uint2*)(par ? g_fh1 : g_fh0);
    int beg = g_rowptr[node];
    int end = g_rowptr[node + 1];
    float4 acc = make_float4(0.f, 0.f, 0.f, 0.f);
    int j = beg;
    for (; j + 2 <= end; j += 2) {
        int2 e0 = g_edge[j];
        int2 e1 = g_edge[j + 1];
        uint2 v0 = in2[(long)e0.x * 32 + lane];
        uint2 v1 = in2[(long)e1.x * 32 + lane];
        float w0 = __int_as_float(e0.y), w1 = __int_as_float(e1.y);
        float2 a0 = __half22float2(*(__half2*)&v0.x);
        float2 a1 = __half22float2(*(__half2*)&v0.y);
        float2 b0 = __half22float2(*(__half2*)&v1.x);
        float2 b1 = __half22float2(*(__half2*)&v1.y);
        acc.x = fmaf(a0.x, w0, fmaf(b0.x, w1, acc.x));
        acc.y = fmaf(a0.y, w0, fmaf(b0.y, w1, acc.y));
        acc.z = fmaf(a1.x, w0, fmaf(b1.x, w1, acc.z));
        acc.w = fmaf(a1.y, w0, fmaf(b1.y, w1, acc.w));
    }
    if (j < end) {
        int2 e0 = g_edge[j];
        uint2 v0 = in2[(long)e0.x * 32 + lane];
        float w0 = __int_as_float(e0.y);
        float2 a0 = __half22float2(*(__half2*)&v0.x);
        float2 a1 = __half22float2(*(__half2*)&v0.y);
        acc.x = fmaf(a0.x, w0, acc.x);
        acc.y = fmaf(a0.y, w0, acc.y);
        acc.z = fmaf(a1.x, w0, acc.z);
        acc.w = fmaf(a1.y, w0, acc.w);
    }
    uint2 o;
    *(__half2*)&o.x = __float22half2_rn(make_float2(acc.x, acc.y));
    *(__half2*)&o.y = __float22half2_rn(make_float2(acc.z, acc.w));
    out2[node * 32 + lane] = o;
}

// ---------------- GEMM1 (fp16 MMA + ldmatrix): h = ft @ W1^T + b1 + BN stats ----------------
#define S1 40   // smem stride in halves: 80B rows -> LDSM phases conflict-free (5l mod 8 distinct)
__global__ __launch_bounds__(256) void k_gemm1(const float* __restrict__ bias) {
    __shared__ __half As[128 * S1];
    __shared__ __half Bs[128 * S1];
    __shared__ float s_bias[128];
    const int tid = threadIdx.x;
    const int m0 = blockIdx.x * 128, n0 = blockIdx.y * 128;
    const int wid = tid >> 5, lane = tid & 31;
    const int g = lane >> 2, t = lane & 3;
    const int wm = (wid & 1) * 64, wn = (wid >> 1) * 32;
    if (tid < 128) s_bias[tid] = bias[n0 + tid];

    float acc[4][4][4];
    #pragma unroll
    for (int i = 0; i < 4; i++)
        #pragma unroll
        for (int j = 0; j < 4; j++)
            #pragma unroll
            for (int r = 0; r < 4; r++) acc[i][j][r] = 0.f;

    // ldmatrix lane-address bases (bytes)
    const unsigned asb = (unsigned)__cvta_generic_to_shared(As);
    const unsigned bsb = (unsigned)__cvta_generic_to_shared(Bs);
    const unsigned aBase = asb + (((wm + (lane & 15)) * S1 + (lane >> 4) * 8) << 1);
    const unsigned bBase = bsb + (((wn + (lane & 7)) * S1 + ((lane >> 3) & 1) * 8) << 1);

    const int lrow = tid >> 1, lkq = (tid & 1) * 16;
    int gr = m0 + lrow; if (gr >= NN) gr = NN - 1;
    const __half* aptr = &g_fh0[gr * FD + lkq];
    const __half* bptr = &g_w1h[(n0 + lrow) * FD + lkq];

    uint4 ra0 = *(const uint4*)(aptr);
    uint4 ra1 = *(const uint4*)(aptr + 8);
    uint4 rb0 = *(const uint4*)(bptr);
    uint4 rb1 = *(const uint4*)(bptr + 8);
    *(uint4*)&As[lrow * S1 + lkq]     = ra0;
    *(uint4*)&As[lrow * S1 + lkq + 8] = ra1;
    *(uint4*)&Bs[lrow * S1 + lkq]     = rb0;
    *(uint4*)&Bs[lrow * S1 + lkq + 8] = rb1;
    __syncthreads();

    for (int kt = 0; kt < FD; kt += 32) {
        bool more = (kt + 32 < FD);
        if (more) {
            ra0 = *(const uint4*)(aptr + kt + 32);
            ra1 = *(const uint4*)(aptr + kt + 40);
            rb0 = *(const uint4*)(bptr + kt + 32);
            rb1 = *(const uint4*)(bptr + kt + 40);
        }
        #pragma unroll
        for (int ks = 0; ks < 32; ks += 16) {
            unsigned bf[4][2];
            #pragma unroll
            for (int j = 0; j < 4; j++)
                ldsm_x2(bf[j], bBase + ((j * 8 * S1 + ks) << 1));
            #pragma unroll
            for (int i = 0; i < 4; i++) {
                unsigned af[4];
                ldsm_x4(af, aBase + ((i * 16 * S1 + ks) << 1));
                #pragma unroll
                for (int j = 0; j < 4; j++) mma_f16(acc[i][j], af, bf[j]);
            }
        }
        __syncthreads();
        if (more) {
            *(uint4*)&As[lrow * S1 + lkq]     = ra0;
            *(uint4*)&As[lrow * S1 + lkq + 8] = ra1;
            *(uint4*)&Bs[lrow * S1 + lkq]     = rb0;
            *(uint4*)&Bs[lrow * S1 + lkq + 8] = rb1;
            __syncthreads();
        }
    }

    // Epilogue: bias, write h (fp16), fused BN partials
    float s0[4] = {0.f,0.f,0.f,0.f}, q0[4] = {0.f,0.f,0.f,0.f};
    float s1[4] = {0.f,0.f,0.f,0.f}, q1[4] = {0.f,0.f,0.f,0.f};
    #pragma unroll
    for (int i = 0; i < 4; i++) {
        int r0 = m0 + wm + 16 * i + g;
        int r1 = r0 + 8;
        #pragma unroll
        for (int j = 0; j < 4; j++) {
            int lc = wn + 8 * j + 2 * t;
            float b0v = s_bias[lc], b1v = s_bias[lc + 1];
            float h00 = acc[i][j][0] + b0v, h01 = acc[i][j][1] + b1v;
            float h10 = acc[i][j][2] + b0v, h11 = acc[i][j][3] + b1v;
            if (r0 < NN) {
                *(__half2*)&g_hh[r0 * NH + n0 + lc] = __float22half2_rn(make_float2(h00, h01));
                s0[j] += h00; q0[j] = fmaf(h00, h00, q0[j]);
                s1[j] += h01; q1[j] = fmaf(h01, h01, q1[j]);
            }
            if (r1 < NN) {
                *(__half2*)&g_hh[r1 * NH + n0 + lc] = __float22half2_rn(make_float2(h10, h11));
                s0[j] += h10; q0[j] = fmaf(h10, h10, q0[j]);
                s1[j] += h11; q1[j] = fmaf(h11, h11, q1[j]);
            }
        }
    }
    #pragma unroll
    for (int j = 0; j < 4; j++) {
        #pragma unroll
        for (int off = 4; off < 32; off <<= 1) {
            s0[j] += __shfl_xor_sync(0xffffffff, s0[j], off);
            q0[j] += __shfl_xor_sync(0xffffffff, q0[j], off);
            s1[j] += __shfl_xor_sync(0xffffffff, s1[j], off);
            q1[j] += __shfl_xor_sync(0xffffffff, q1[j], off);
        }
    }
    if (lane < 4) {
        #pragma unroll
        for (int j = 0; j < 4; j++) {
            int col = n0 + wn + 8 * j + 2 * lane;
            atomicAdd(&g_colsum[col],     s0[j]);
            atomicAdd(&g_colsum[col + 1], s1[j]);
            atomicAdd(&g_colsq[col],      q0[j]);
            atomicAdd(&g_colsq[col + 1],  q1[j]);
        }
    }
}

// ---------------- GEMM2 (fp16 MMA + ldmatrix): out = relu(h*sc+sh) @ W2^T + b2 ----------------
__global__ __launch_bounds__(256) void k_gemm2(const float* __restrict__ gamma,
                                               const float* __restrict__ beta,
                                               const float* __restrict__ b2,
                                               float* __restrict__ out) {
    __shared__ __half As[128 * S1];
    __shared__ __half Bs[64 * S1];
    __shared__ float s_scale[NH];
    __shared__ float s_shift[NH];
    __shared__ float s_b2[NC];
    const int tid = threadIdx.x;
    const int m0 = blockIdx.x * 128;
    const int wid = tid >> 5, lane = tid & 31;
    const int g = lane >> 2, t = lane & 3;
    const int wm = (wid & 3) * 32, wn = (wid >> 2) * 32;
    // BN finalize (redundant per block)
    for (int i = tid; i < NH; i += 256) {
        float mean = g_colsum[i] * (1.0f / NN);
        float var  = g_colsq[i] * (1.0f / NN) - mean * mean;
        float sc = gamma[i] * rsqrtf(var + 1e-5f);
        s_scale[i] = sc;
        s_shift[i] = beta[i] - mean * sc;
    }
    if (tid < NC) s_b2[tid] = b2[tid];

    float acc[2][4][4];
    #pragma unroll
    for (int i = 0; i < 2; i++)
        #pragma unroll
        for (int j = 0; j < 4; j++)
            #pragma unroll
            for (int r = 0; r < 4; r++) acc[i][j][r] = 0.f;

    const unsigned asb = (unsigned)__cvta_generic_to_shared(As);
    const unsigned bsb = (unsigned)__cvta_generic_to_shared(Bs);
    const unsigned aBase = asb + (((wm + (lane & 15)) * S1 + (lane >> 4) * 8) << 1);
    const unsigned bBase = bsb + (((wn + (lane & 7)) * S1 + ((lane >> 3) & 1) * 8) << 1);

    const int lrow = tid >> 1, lkq = (tid & 1) * 16;
    const int brow = tid >> 2, bkq = (tid & 3) * 8;
    int gr = m0 + lrow; if (gr >= NN) gr = NN - 1;
    const __half* aptr = &g_hh[gr * NH + lkq];
    const __half* bptr = &g_w2h[brow * NH + bkq];

    uint4 ra0 = *(const uint4*)(aptr);
    uint4 ra1 = *(const uint4*)(aptr + 8);
    uint4 rb0 = *(const uint4*)(bptr);
    __syncthreads();   // s_scale/s_shift ready

    {
        unsigned res[8];
        const unsigned* vp = (const unsigned*)&ra0;
        #pragma unroll
        for (int p = 0; p < 4; p++) {
            int k = lkq + p * 2;
            float2 f = __half22float2(*(__half2*)&vp[p]);
            f.x = fmaxf(fmaf(f.x, s_scale[k],     s_shift[k]),     0.f);
            f.y = fmaxf(fmaf(f.y, s_scale[k + 1], s_shift[k + 1]), 0.f);
            __half2 h = __float22half2_rn(f);
            res[p] = *(unsigned*)&h;
        }
        const unsigned* wq = (const unsigned*)&ra1;
        #pragma unroll
        for (int p = 0; p < 4; p++) {
            int k = lkq + 8 + p * 2;
            float2 f = __half22float2(*(__half2*)&wq[p]);
            f.x = fmaxf(fmaf(f.x, s_scale[k],     s_shift[k]),     0.f);
            f.y = fmaxf(fmaf(f.y, s_scale[k + 1], s_shift[k + 1]), 0.f);
            __half2 h = __float22half2_rn(f);
            res[p + 4] = *(unsigned*)&h;
        }
        *(uint4*)&As[lrow * S1 + lkq]     = *(uint4*)&res[0];
        *(uint4*)&As[lrow * S1 + lkq + 8] = *(uint4*)&res[4];
        *(uint4*)&Bs[brow * S1 + bkq] = rb0;
    }
    __syncthreads();

    for (int kt = 0; kt < NH; kt += 32) {
        bool more = (kt + 32 < NH);
        if (more) {
            ra0 = *(const uint4*)(aptr + kt + 32);
            ra1 = *(const uint4*)(aptr + kt + 40);
            rb0 = *(const uint4*)(bptr + kt + 32);
        }
        #pragma unroll
        for (int ks = 0; ks < 32; ks += 16) {
            unsigned bf[4][2];
            #pragma unroll
            for (int j = 0; j < 4; j++)
                ldsm_x2(bf[j], bBase + ((j * 8 * S1 + ks) << 1));
            #pragma unroll
            for (int i = 0; i < 2; i++) {
                unsigned af[4];
                ldsm_x4(af, aBase + ((i * 16 * S1 + ks) << 1));
                #pragma unroll
                for (int j = 0; j < 4; j++) mma_f16(acc[i][j], af, bf[j]);
            }
        }
        __syncthreads();
        if (more) {
            int kb = kt + 32;
            unsigned res[8];
            const unsigned* vp = (const unsigned*)&ra0;
            #pragma unroll
            for (int p = 0; p < 4; p++) {
                int k = kb + lkq + p * 2;
                float2 f = __half22float2(*(__half2*)&vp[p]);
                f.x = fmaxf(fmaf(f.x, s_scale[k],     s_shift[k]),     0.f);
                f.y = fmaxf(fmaf(f.y, s_scale[k + 1], s_shift[k + 1]), 0.f);
                __half2 h = __float22half2_rn(f);
                res[p] = *(unsigned*)&h;
            }
            const unsigned* wq = (const unsigned*)&ra1;
            #pragma unroll
            for (int p = 0; p < 4; p++) {
                int k = kb + lkq + 8 + p * 2;
                float2 f = __half22float2(*(__half2*)&wq[p]);
                f.x = fmaxf(fmaf(f.x, s_scale[k],     s_shift[k]),     0.f);
                f.y = fmaxf(fmaf(f.y, s_scale[k + 1], s_shift[k + 1]), 0.f);
                __half2 h = __float22half2_rn(f);
                res[p + 4] = *(unsigned*)&h;
            }
            *(uint4*)&As[lrow * S1 + lkq]     = *(uint4*)&res[0];
            *(uint4*)&As[lrow * S1 + lkq + 8] = *(uint4*)&res[4];
            *(uint4*)&Bs[brow * S1 + bkq] = rb0;
            __syncthreads();
        }
    }
    #pragma unroll
    for (int i = 0; i < 2; i++) {
        int r0 = m0 + wm + 16 * i + g;
        int r1 = r0 + 8;
        #pragma unroll
        for (int j = 0; j < 4; j++) {
            int col = wn + 8 * j + 2 * t;
            float b0v = s_b2[col], b1v = s_b2[col + 1];
            if (r0 < NN)
                *(float2*)&out[r0 * NC + col] = make_float2(acc[i][j][0] + b0v, acc[i][j][1] + b1v);
            if (r1 < NN)
                *(float2*)&out[r1 * NC + col] = make_float2(acc[i][j][2] + b0v, acc[i][j][3] + b1v);
        }
    }
}

// ---------------- host launch ----------------
extern "C" void kernel_launch(void* const* d_in, const int* in_sizes, int n_in,
                              void* d_out, int out_size) {
    const float* feat   = (const float*)d_in[0];
    const int*   src    = (const int*)d_in[1];
    const int*   dst    = (const int*)d_in[2];
    const float* nrm    = (const float*)d_in[3];
    const float* fc1_w  = (const float*)d_in[4];
    const float* fc1_b  = (const float*)d_in[5];
    const float* gamma  = (const float*)d_in[6];
    const float* beta   = (const float*)d_in[7];
    const float* fc2_w  = (const float*)d_in[8];
    const float* fc2_b  = (const float*)d_in[9];
    float* out = (float*)d_out;

    k_cvt<<<(NN * FD / 2 + 255) / 256, 256>>>(feat, fc1_w, fc2_w);
    k_hist<<<(NE + 255) / 256, 256>>>(dst);
    k_scan1<<<SCAN_BLOCKS, 1024>>>();
    k_scan23<<<SCAN_BLOCKS, 1024>>>();
    k_scatter<<<(NE + 255) / 256, 256>>>(src, dst, nrm);

    int prop_blocks = (NN * 32 + 255) / 256;
    k_prop<<<prop_blocks, 256>>>(0);
    k_prop<<<prop_blocks, 256>>>(1);
    k_prop<<<prop_blocks, 256>>>(0);

    dim3 g1((NN + 127) / 128, NH / 128);
    k_gemm1<<<g1, 256>>>(fc1_b);
    k_gemm2<<<(NN + 127) / 128, 256>>>(gamma, beta, fc2_b, out);
}

// round 9
// speedup vs baseline: 1.0189x; 1.0189x over previous
#include <cuda_runtime.h>
#include <cuda_fp16.h>

#define NN 100000
#define NE 1600000
#define FD 128
#define NH 512
#define NC 64
#define SCAN_BLOCKS 98   // ceil(100000/1024)
#define NSLOT 8

// ---------------- device scratch ----------------
__device__ int    g_deg[NN + 1];
__device__ int    g_rowptr[NN + 1];
__device__ int    g_cursor[NN];
__device__ int2   g_edge[NE];       // (src, wgt bits) interleaved
__device__ __half g_fh0[NN * FD];
__device__ __half g_fh1[NN * FD];
__device__ __half g_hh[NN * NH];
__device__ __half g_w1h[NH * FD];   // fc1_w as fp16
__device__ __half g_w2h[NC * NH];   // fc2_w as fp16
__device__ float  g_colsum[NSLOT * NH];
__device__ float  g_colsq[NSLOT * NH];
// decoupled-lookback scan state
__device__ volatile int g_flag[SCAN_BLOCKS];
__device__ volatile int g_agg[SCAN_BLOCKS];
__device__ volatile int g_pre[SCAN_BLOCKS];

// ---------------- mma / ldmatrix helpers ----------------
__device__ __forceinline__ void mma_f16(float* c, const unsigned* a, const unsigned* b) {
    asm volatile(
        "mma.sync.aligned.m16n8k16.row.col.f32.f16.f16.f32 "
        "{%0,%1,%2,%3}, {%4,%5,%6,%7}, {%8,%9}, {%0,%1,%2,%3};"
        : "+f"(c[0]), "+f"(c[1]), "+f"(c[2]), "+f"(c[3])
        : "r"(a[0]), "r"(a[1]), "r"(a[2]), "r"(a[3]), "r"(b[0]), "r"(b[1]));
}

__device__ __forceinline__ void ldsm_x4(unsigned* r, unsigned addr) {
    asm volatile("ldmatrix.sync.aligned.m8n8.x4.shared.b16 {%0,%1,%2,%3}, [%4];"
                 : "=r"(r[0]), "=r"(r[1]), "=r"(r[2]), "=r"(r[3]) : "r"(addr));
}

__device__ __forceinline__ void ldsm_x2(unsigned* r, unsigned addr) {
    asm volatile("ldmatrix.sync.aligned.m8n8.x2.shared.b16 {%0,%1}, [%2];"
                 : "=r"(r[0]), "=r"(r[1]) : "r"(addr));
}

// ---------------- cvt + zero ----------------
__global__ void k_cvt(const float* __restrict__ feat,
                      const float* __restrict__ w1,
                      const float* __restrict__ w2) {
    int i = blockIdx.x * blockDim.x + threadIdx.x;
    if (i < NN * FD / 2) {
        float2 v = ((const float2*)feat)[i];
        ((__half2*)g_fh1)[i] = __float22half2_rn(v);
    }
    if (i < NH * FD / 2) {
        float2 v = ((const float2*)w1)[i];
        ((__half2*)g_w1h)[i] = __float22half2_rn(v);
    }
    if (i < NC * NH / 2) {
        float2 v = ((const float2*)w2)[i];
        ((__half2*)g_w2h)[i] = __float22half2_rn(v);
    }
    if (i < NN + 1) g_deg[i] = 0;
    if (i < NSLOT * NH) { g_colsum[i] = 0.f; g_colsq[i] = 0.f; }
    if (i < SCAN_BLOCKS) g_flag[i] = 0;
}

// ---------------- CSR build ----------------
__global__ void k_hist(const int* __restrict__ dst) {
    int e4 = blockIdx.x * blockDim.x + threadIdx.x;
    if (e4 < NE / 4) {
        int4 d = ((const int4*)dst)[e4];
        atomicAdd(&g_deg[d.x], 1);
        atomicAdd(&g_deg[d.y], 1);
        atomicAdd(&g_deg[d.z], 1);
        atomicAdd(&g_deg[d.w], 1);
    }
}

// single-pass scan with warp-parallel decoupled lookback (98 blocks all resident)
__global__ void k_scan() {
    __shared__ int sh[1024];
    __shared__ int s_excl;
    const int bid = blockIdx.x;
    int i = bid * 1024 + threadIdx.x;
    int v = (i < NN) ? g_deg[i] : 0;
    sh[threadIdx.x] = v;
    __syncthreads();
    #pragma unroll
    for (int off = 1; off < 1024; off <<= 1) {
        int t = (threadIdx.x >= off) ? sh[threadIdx.x - off] : 0;
        __syncthreads();
        sh[threadIdx.x] += t;
        __syncthreads();
    }
    int agg = sh[1023];
    if (threadIdx.x >= 992) {
        int lane = threadIdx.x - 992;
        if (bid == 0) {
            if (lane == 0) {
                g_pre[0] = agg;
                __threadfence();
                g_flag[0] = 2;
                s_excl = 0;
            }
        } else {
            if (lane == 0) {
                g_agg[bid] = agg;
                __threadfence();
                g_flag[bid] = 1;
            }
            __syncwarp();
            int excl = 0;
            int j = bid - 1;
            while (true) {
                int idx = j - lane;
                int f = 0, val = 0;
                if (idx >= 0) {
                    do { f = g_flag[idx]; } while (f == 0);
                    __threadfence();
                    val = (f == 2) ? g_pre[idx] : g_agg[idx];
                }
                unsigned pm = __ballot_sync(0xffffffff, (idx >= 0) && (f == 2));
                int stop = __ffs(pm) - 1;   // -1 if no prefix seen in this window
                int take = (idx >= 0) && (stop < 0 || lane <= stop);
                int contrib = take ? val : 0;
                #pragma unroll
                for (int o = 16; o; o >>= 1)
                    contrib += __shfl_down_sync(0xffffffff, contrib, o);
                excl += __shfl_sync(0xffffffff, contrib, 0);
                if (stop >= 0) break;
                j -= 32;
            }
            if (lane == 0) {
                g_pre[bid] = excl + agg;
                __threadfence();
                g_flag[bid] = 2;
                s_excl = excl;
            }
        }
    }
    __syncthreads();
    int base = (bid == 0) ? 0 : s_excl;
    if (i < NN) {
        int excl_i = sh[threadIdx.x] - v + base;
        g_rowptr[i] = excl_i;
        g_cursor[i] = excl_i;
        if (i == NN - 1) g_rowptr[NN] = sh[threadIdx.x] + base;
    }
}

__global__ void k_scatter(const int* __restrict__ src, const int* __restrict__ dst,
                          const float* __restrict__ nrm) {
    int e = blockIdx.x * blockDim.x + threadIdx.x;
    if (e < NE) {
        int d = dst[e];
        int pos = atomicAdd(&g_cursor[d], 1);
        g_edge[pos] = make_int2(src[e], __float_as_int(nrm[e]));
    }
}

// ---------------- K-hop propagation: warp per dst, fp16 rows, fp32 accum (unroll-2) ----------------
__global__ void k_prop(int par) {
    int gt = blockIdx.x * blockDim.x + threadIdx.x;
    int node = gt >> 5;
    int lane = gt & 31;
    if (node >= NN) return;
    const uint2* in2  = (const uint2*)(par ? g_fh0 : g_fh1);
    uint2*       out2 = (uint2*)(par ? g_fh1 : g_fh0);
    int beg = g_rowptr[node];
    int end = g_rowptr[node + 1];
    float4 acc = make_float4(0.f, 0.f, 0.f, 0.f);
    int j = beg;
    for (; j + 2 <= end; j += 2) {
        int2 e0 = g_edge[j];
        int2 e1 = g_edge[j + 1];
        uint2 v0 = in2[(long)e0.x * 32 + lane];
        uint2 v1 = in2[(long)e1.x * 32 + lane];
        float w0 = __int_as_float(e0.y), w1 = __int_as_float(e1.y);
        float2 a0 = __half22float2(*(__half2*)&v0.x);
        float2 a1 = __half22float2(*(__half2*)&v0.y);
        float2 b0 = __half22float2(*(__half2*)&v1.x);
        float2 b1 = __half22float2(*(__half2*)&v1.y);
        acc.x = fmaf(a0.x, w0, fmaf(b0.x, w1, acc.x));
        acc.y = fmaf(a0.y, w0, fmaf(b0.y, w1, acc.y));
        acc.z = fmaf(a1.x, w0, fmaf(b1.x, w1, acc.z));
        acc.w = fmaf(a1.y, w0, fmaf(b1.y, w1, acc.w));
    }
    if (j < end) {
        int2 e0 = g_edge[j];
        uint2 v0 = in2[(long)e0.x * 32 + lane];
        float w0 = __int_as_float(e0.y);
        float2 a0 = __half22float2(*(__half2*)&v0.x);
        float2 a1 = __half22float2(*(__half2*)&v0.y);
        acc.x = fmaf(a0.x, w0, acc.x);
        acc.y = fmaf(a0.y, w0, acc.y);
        acc.z = fmaf(a1.x, w0, acc.z);
        acc.w = fmaf(a1.y, w0, acc.w);
    }
    uint2 o;
    *(__half2*)&o.x = __float22half2_rn(make_float2(acc.x, acc.y));
    *(__half2*)&o.y = __float22half2_rn(make_float2(acc.z, acc.w));
    out2[node * 32 + lane] = o;
}

// ---------------- GEMM1 (fp16 MMA + ldmatrix): h = ft @ W1^T + b1 + BN stats ----------------
#define S1 40   // smem stride in halves: 80B rows -> LDSM phases conflict-free
__global__ __launch_bounds__(256) void k_gemm1(const float* __restrict__ bias) {
    __shared__ __half As[128 * S1];
    __shared__ __half Bs[128 * S1];
    __shared__ float s_bias[128];
    const int tid = threadIdx.x;
    const int m0 = blockIdx.x * 128, n0 = blockIdx.y * 128;
    const int wid = tid >> 5, lane = tid & 31;
    const int g = lane >> 2, t = lane & 3;
    const int wm = (wid & 1) * 64, wn = (wid >> 1) * 32;
    if (tid < 128) s_bias[tid] = bias[n0 + tid];

    float acc[4][4][4];
    #pragma unroll
    for (int i = 0; i < 4; i++)
        #pragma unroll
        for (int j = 0; j < 4; j++)
            #pragma unroll
            for (int r = 0; r < 4; r++) acc[i][j][r] = 0.f;

    const unsigned asb = (unsigned)__cvta_generic_to_shared(As);
    const unsigned bsb = (unsigned)__cvta_generic_to_shared(Bs);
    const unsigned aBase = asb + (((wm + (lane & 15)) * S1 + (lane >> 4) * 8) << 1);
    const unsigned bBase = bsb + (((wn + (lane & 7)) * S1 + ((lane >> 3) & 1) * 8) << 1);

    const int lrow = tid >> 1, lkq = (tid & 1) * 16;
    int gr = m0 + lrow; if (gr >= NN) gr = NN - 1;
    const __half* aptr = &g_fh0[gr * FD + lkq];
    const __half* bptr = &g_w1h[(n0 + lrow) * FD + lkq];

    uint4 ra0 = *(const uint4*)(aptr);
    uint4 ra1 = *(const uint4*)(aptr + 8);
    uint4 rb0 = *(const uint4*)(bptr);
    uint4 rb1 = *(const uint4*)(bptr + 8);
    *(uint4*)&As[lrow * S1 + lkq]     = ra0;
    *(uint4*)&As[lrow * S1 + lkq + 8] = ra1;
    *(uint4*)&Bs[lrow * S1 + lkq]     = rb0;
    *(uint4*)&Bs[lrow * S1 + lkq + 8] = rb1;
    __syncthreads();

    for (int kt = 0; kt < FD; kt += 32) {
        bool more = (kt + 32 < FD);
        if (more) {
            ra0 = *(const uint4*)(aptr + kt + 32);
            ra1 = *(const uint4*)(aptr + kt + 40);
            rb0 = *(const uint4*)(bptr + kt + 32);
            rb1 = *(const uint4*)(bptr + kt + 40);
        }
        #pragma unroll
        for (int ks = 0; ks < 32; ks += 16) {
            unsigned bf[4][2];
            #pragma unroll
            for (int j = 0; j < 4; j++)
                ldsm_x2(bf[j], bBase + ((j * 8 * S1 + ks) << 1));
            #pragma unroll
            for (int i = 0; i < 4; i++) {
                unsigned af[4];
                ldsm_x4(af, aBase + ((i * 16 * S1 + ks) << 1));
                #pragma unroll
                for (int j = 0; j < 4; j++) mma_f16(acc[i][j], af, bf[j]);
            }
        }
        __syncthreads();
        if (more) {
            *(uint4*)&As[lrow * S1 + lkq]     = ra0;
            *(uint4*)&As[lrow * S1 + lkq + 8] = ra1;
            *(uint4*)&Bs[lrow * S1 + lkq]     = rb0;
            *(uint4*)&Bs[lrow * S1 + lkq + 8] = rb1;
            __syncthreads();
        }
    }

    // Epilogue: bias, write h (fp16), fused BN partials -> slotted atomics
    float s0[4] = {0.f,0.f,0.f,0.f}, q0[4] = {0.f,0.f,0.f,0.f};
    float s1[4] = {0.f,0.f,0.f,0.f}, q1[4] = {0.f,0.f,0.f,0.f};
    #pragma unroll
    for (int i = 0; i < 4; i++) {
        int r0 = m0 + wm + 16 * i + g;
        int r1 = r0 + 8;
        #pragma unroll
        for (int j = 0; j < 4; j++) {
            int lc = wn + 8 * j + 2 * t;
            float b0v = s_bias[lc], b1v = s_bias[lc + 1];
            float h00 = acc[i][j][0] + b0v, h01 = acc[i][j][1] + b1v;
            float h10 = acc[i][j][2] + b0v, h11 = acc[i][j][3] + b1v;
            if (r0 < NN) {
                *(__half2*)&g_hh[r0 * NH + n0 + lc] = __float22half2_rn(make_float2(h00, h01));
                s0[j] += h00; q0[j] = fmaf(h00, h00, q0[j]);
                s1[j] += h01; q1[j] = fmaf(h01, h01, q1[j]);
            }
            if (r1 < NN) {
                *(__half2*)&g_hh[r1 * NH + n0 + lc] = __float22half2_rn(make_float2(h10, h11));
                s0[j] += h10; q0[j] = fmaf(h10, h10, q0[j]);
                s1[j] += h11; q1[j] = fmaf(h11, h11, q1[j]);
            }
        }
    }
    #pragma unroll
    for (int j = 0; j < 4; j++) {
        #pragma unroll
        for (int off = 4; off < 32; off <<= 1) {
            s0[j] += __shfl_xor_sync(0xffffffff, s0[j], off);
            q0[j] += __shfl_xor_sync(0xffffffff, q0[j], off);
            s1[j] += __shfl_xor_sync(0xffffffff, s1[j], off);
            q1[j] += __shfl_xor_sync(0xffffffff, q1[j], off);
        }
    }
    if (lane < 4) {
        int slot = ((blockIdx.x ^ wid) & (NSLOT - 1)) * NH;
        #pragma unroll
        for (int j = 0; j < 4; j++) {
            int col = n0 + wn + 8 * j + 2 * lane;
            atomicAdd(&g_colsum[slot + col],     s0[j]);
            atomicAdd(&g_colsum[slot + col + 1], s1[j]);
            atomicAdd(&g_colsq[slot + col],      q0[j]);
            atomicAdd(&g_colsq[slot + col + 1],  q1[j]);
        }
    }
}

// ---------------- GEMM2 (fp16 MMA + ldmatrix): out = relu(h*sc+sh) @ W2^T + b2 ----------------
__global__ __launch_bounds__(256) void k_gemm2(const float* __restrict__ gamma,
                                               const float* __restrict__ beta,
                                               const float* __restrict__ b2,
                                               float* __restrict__ out) {
    __shared__ __half As[128 * S1];
    __shared__ __half Bs[64 * S1];
    __shared__ float s_scale[NH];
    __shared__ float s_shift[NH];
    __shared__ float s_b2[NC];
    const int tid = threadIdx.x;
    const int m0 = blockIdx.x * 128;
    const int wid = tid >> 5, lane = tid & 31;
    const int g = lane >> 2, t = lane & 3;
    const int wm = (wid & 3) * 32, wn = (wid >> 2) * 32;
    // BN finalize from slotted partials (redundant per block)
    for (int i = tid; i < NH; i += 256) {
        float s = 0.f, q = 0.f;
        #pragma unroll
        for (int r = 0; r < NSLOT; r++) { s += g_colsum[r * NH + i]; q += g_colsq[r * NH + i]; }
        float mean = s * (1.0f / NN);
        float var  = q * (1.0f / NN) - mean * mean;
        float sc = gamma[i] * rsqrtf(var + 1e-5f);
        s_scale[i] = sc;
        s_shift[i] = beta[i] - mean * sc;
    }
    if (tid < NC) s_b2[tid] = b2[tid];

    float acc[2][4][4];
    #pragma unroll
    for (int i = 0; i < 2; i++)
        #pragma unroll
        for (int j = 0; j < 4; j++)
            #pragma unroll
            for (int r = 0; r < 4; r++) acc[i][j][r] = 0.f;

    const unsigned asb = (unsigned)__cvta_generic_to_shared(As);
    const unsigned bsb = (unsigned)__cvta_generic_to_shared(Bs);
    const unsigned aBase = asb + (((wm + (lane & 15)) * S1 + (lane >> 4) * 8) << 1);
    const unsigned bBase = bsb + (((wn + (lane & 7)) * S1 + ((lane >> 3) & 1) * 8) << 1);

    const int lrow = tid >> 1, lkq = (tid & 1) * 16;
    const int brow = tid >> 2, bkq = (tid & 3) * 8;
    int gr = m0 + lrow; if (gr >= NN) gr = NN - 1;
    const __half* aptr = &g_hh[gr * NH + lkq];
    const __half* bptr = &g_w2h[brow * NH + bkq];

    uint4 ra0 = *(const uint4*)(aptr);
    uint4 ra1 = *(const uint4*)(aptr + 8);
    uint4 rb0 = *(const uint4*)(bptr);
    __syncthreads();   // s_scale/s_shift ready

    {
        unsigned res[8];
        const unsigned* vp = (const unsigned*)&ra0;
        #pragma unroll
        for (int p = 0; p < 4; p++) {
            int k = lkq + p * 2;
            float2 f = __half22float2(*(__half2*)&vp[p]);
            f.x = fmaxf(fmaf(f.x, s_scale[k],     s_shift[k]),     0.f);
            f.y = fmaxf(fmaf(f.y, s_scale[k + 1], s_shift[k + 1]), 0.f);
            __half2 h = __float22half2_rn(f);
            res[p] = *(unsigned*)&h;
        }
        const unsigned* wq = (const unsigned*)&ra1;
        #pragma unroll
        for (int p = 0; p < 4; p++) {
            int k = lkq + 8 + p * 2;
            float2 f = __half22float2(*(__half2*)&wq[p]);
            f.x = fmaxf(fmaf(f.x, s_scale[k],     s_shift[k]),     0.f);
            f.y = fmaxf(fmaf(f.y, s_scale[k + 1], s_shift[k + 1]), 0.f);
            __half2 h = __float22half2_rn(f);
            res[p + 4] = *(unsigned*)&h;
        }
        *(uint4*)&As[lrow * S1 + lkq]     = *(uint4*)&res[0];
        *(uint4*)&As[lrow * S1 + lkq + 8] = *(uint4*)&res[4];
        *(uint4*)&Bs[brow * S1 + bkq] = rb0;
    }
    __syncthreads();

    for (int kt = 0; kt < NH; kt += 32) {
        bool more = (kt + 32 < NH);
        if (more) {
            ra0 = *(const uint4*)(aptr + kt + 32);
            ra1 = *(const uint4*)(aptr + kt + 40);
            rb0 = *(const uint4*)(bptr + kt + 32);
        }
        #pragma unroll
        for (int ks = 0; ks < 32; ks += 16) {
            unsigned bf[4][2];
            #pragma unroll
            for (int j = 0; j < 4; j++)
                ldsm_x2(bf[j], bBase + ((j * 8 * S1 + ks) << 1));
            #pragma unroll
            for (int i = 0; i < 2; i++) {
                unsigned af[4];
                ldsm_x4(af, aBase + ((i * 16 * S1 + ks) << 1));
                #pragma unroll
                for (int j = 0; j < 4; j++) mma_f16(acc[i][j], af, bf[j]);
            }
        }
        __syncthreads();
        if (more) {
            int kb = kt + 32;
            unsigned res[8];
            const unsigned* vp = (const unsigned*)&ra0;
            #pragma unroll
            for (int p = 0; p < 4; p++) {
                int k = kb + lkq + p * 2;
                float2 f = __half22float2(*(__half2*)&vp[p]);
                f.x = fmaxf(fmaf(f.x, s_scale[k],     s_shift[k]),     0.f);
                f.y = fmaxf(fmaf(f.y, s_scale[k + 1], s_shift[k + 1]), 0.f);
                __half2 h = __float22half2_rn(f);
                res[p] = *(unsigned*)&h;
            }
            const unsigned* wq = (const unsigned*)&ra1;
            #pragma unroll
            for (int p = 0; p < 4; p++) {
                int k = kb + lkq + 8 + p * 2;
                float2 f = __half22float2(*(__half2*)&wq[p]);
                f.x = fmaxf(fmaf(f.x, s_scale[k],     s_shift[k]),     0.f);
                f.y = fmaxf(fmaf(f.y, s_scale[k + 1], s_shift[k + 1]), 0.f);
                __half2 h = __float22half2_rn(f);
                res[p + 4] = *(unsigned*)&h;
            }
            *(uint4*)&As[lrow * S1 + lkq]     = *(uint4*)&res[0];
            *(uint4*)&As[lrow * S1 + lkq + 8] = *(uint4*)&res[4];
            *(uint4*)&Bs[brow * S1 + bkq] = rb0;
            __syncthreads();
        }
    }
    #pragma unroll
    for (int i = 0; i < 2; i++) {
        int r0 = m0 + wm + 16 * i + g;
        int r1 = r0 + 8;
        #pragma unroll
        for (int j = 0; j < 4; j++) {
            int col = wn + 8 * j + 2 * t;
            float b0v = s_b2[col], b1v = s_b2[col + 1];
            if (r0 < NN)
                *(float2*)&out[r0 * NC + col] = make_float2(acc[i][j][0] + b0v, acc[i][j][1] + b1v);
            if (r1 < NN)
                *(float2*)&out[r1 * NC + col] = make_float2(acc[i][j][2] + b0v, acc[i][j][3] + b1v);
        }
    }
}

// ---------------- host launch ----------------
extern "C" void kernel_launch(void* const* d_in, const int* in_sizes, int n_in,
                              void* d_out, int out_size) {
    const float* feat   = (const float*)d_in[0];
    const int*   src    = (const int*)d_in[1];
    const int*   dst    = (const int*)d_in[2];
    const float* nrm    = (const float*)d_in[3];
    const float* fc1_w  = (const float*)d_in[4];
    const float* fc1_b  = (const float*)d_in[5];
    const float* gamma  = (const float*)d_in[6];
    const float* beta   = (const float*)d_in[7];
    const float* fc2_w  = (const float*)d_in[8];
    const float* fc2_b  = (const float*)d_in[9];
    float* out = (float*)d_out;

    k_cvt<<<(NN * FD / 2 + 255) / 256, 256>>>(feat, fc1_w, fc2_w);
    k_hist<<<(NE / 4 + 255) / 256, 256>>>(dst);
    k_scan<<<SCAN_BLOCKS, 1024>>>();
    k_scatter<<<(NE + 255) / 256, 256>>>(src, dst, nrm);

    int prop_blocks = (NN * 32 + 255) / 256;
    k_prop<<<prop_blocks, 256>>>(0);
    k_prop<<<prop_blocks, 256>>>(1);
    k_prop<<<prop_blocks, 256>>>(0);

    dim3 g1((NN + 127) / 128, NH / 128);
    k_gemm1<<<g1, 256>>>(fc1_b);
    k_gemm2<<<(NN + 127) / 128, 256>>>(gamma, beta, fc2_b, out);
}

// round 10
// speedup vs baseline: 1.0190x; 1.0001x over previous
#include <cuda_runtime.h>
#include <cuda_fp16.h>

#define NN 100000
#define NE 1600000
#define FD 128
#define NH 512
#define NC 64
#define SCAN_BLOCKS 98   // ceil(100000/1024)
#define NSLOT 8

// ---------------- device scratch ----------------
__device__ int    g_deg[NN + 1];
__device__ int    g_rowptr[NN + 1];
__device__ int    g_cursor[NN];
__device__ int2   g_edge[NE];       // (src, wgt bits) interleaved
__device__ __half g_fh0[NN * FD];
__device__ __half g_fh1[NN * FD];
__device__ __half g_hh[NN * NH];
__device__ __half g_w1h[NH * FD];   // fc1_w as fp16
__device__ __half g_w2h[NC * NH];   // fc2_w as fp16
__device__ float  g_colsum[NSLOT * NH];
__device__ float  g_colsq[NSLOT * NH];
// decoupled-lookback scan state
__device__ volatile int g_flag[SCAN_BLOCKS];
__device__ volatile int g_agg[SCAN_BLOCKS];
__device__ volatile int g_pre[SCAN_BLOCKS];

// ---------------- mma / ldmatrix helpers ----------------
__device__ __forceinline__ void mma_f16(float* c, const unsigned* a, const unsigned* b) {
    asm volatile(
        "mma.sync.aligned.m16n8k16.row.col.f32.f16.f16.f32 "
        "{%0,%1,%2,%3}, {%4,%5,%6,%7}, {%8,%9}, {%0,%1,%2,%3};"
        : "+f"(c[0]), "+f"(c[1]), "+f"(c[2]), "+f"(c[3])
        : "r"(a[0]), "r"(a[1]), "r"(a[2]), "r"(a[3]), "r"(b[0]), "r"(b[1]));
}

__device__ __forceinline__ void ldsm_x4(unsigned* r, unsigned addr) {
    asm volatile("ldmatrix.sync.aligned.m8n8.x4.shared.b16 {%0,%1,%2,%3}, [%4];"
                 : "=r"(r[0]), "=r"(r[1]), "=r"(r[2]), "=r"(r[3]) : "r"(addr));
}

__device__ __forceinline__ void ldsm_x2(unsigned* r, unsigned addr) {
    asm volatile("ldmatrix.sync.aligned.m8n8.x2.shared.b16 {%0,%1}, [%2];"
                 : "=r"(r[0]), "=r"(r[1]) : "r"(addr));
}

// ---------------- cvt + zero + hist (merged; all independent elementwise work) ----------------
__global__ void k_cvt(const float* __restrict__ feat,
                      const float* __restrict__ w1,
                      const float* __restrict__ w2,
                      const int* __restrict__ dst) {
    int i = blockIdx.x * blockDim.x + threadIdx.x;
    if (i < NN * FD / 2) {
        float2 v = ((const float2*)feat)[i];
        ((__half2*)g_fh1)[i] = __float22half2_rn(v);
    }
    if (i < NH * FD / 2) {
        float2 v = ((const float2*)w1)[i];
        ((__half2*)g_w1h)[i] = __float22half2_rn(v);
    }
    if (i < NC * NH / 2) {
        float2 v = ((const float2*)w2)[i];
        ((__half2*)g_w2h)[i] = __float22half2_rn(v);
    }
    if (i < NN + 1) g_deg[i] = 0;
    if (i < NSLOT * NH) { g_colsum[i] = 0.f; g_colsq[i] = 0.f; }
    if (i < SCAN_BLOCKS) g_flag[i] = 0;
    // histogram (after a grid-wide implicit dependency? No — deg zeroing happens
    // in this same kernel; ensure the zeroing threads cover deg BEFORE any atomics
    // could race. Zeroing and atomics on g_deg in the same grid would race, so
    // hist must use a separate pre-zeroed epoch: we zero in the FIRST wave via
    // a grid-stride split: threads zero deg first (above), and hist atomics are
    // issued only by threads whose zero targets are already done. To stay safe,
    // hist goes below on a disjoint index range computed AFTER __threadfence?
    // Simpler and safe: hist handled in k_scan prologue is not possible.
    // => keep hist here but on g_deg2-free design: zeroing is done by threads
    //    i < NN+1 and hist atomics also come from this grid. Blocks run
    //    concurrently, so a hist atomic could land before another block zeroes
    //    that counter. AVOID: do hist in k_scan's producer pass instead.
}

// hist folded into its own kernel remains (race-free): 4 edges/thread
__global__ void k_hist(const int* __restrict__ dst) {
    int e4 = blockIdx.x * blockDim.x + threadIdx.x;
    if (e4 < NE / 4) {
        int4 d = ((const int4*)dst)[e4];
        atomicAdd(&g_deg[d.x], 1);
        atomicAdd(&g_deg[d.y], 1);
        atomicAdd(&g_deg[d.z], 1);
        atomicAdd(&g_deg[d.w], 1);
    }
}

// single-pass scan with warp-parallel decoupled lookback (98 blocks all resident)
__global__ void k_scan() {
    __shared__ int sh[1024];
    __shared__ int s_excl;
    const int bid = blockIdx.x;
    int i = bid * 1024 + threadIdx.x;
    int v = (i < NN) ? g_deg[i] : 0;
    sh[threadIdx.x] = v;
    __syncthreads();
    #pragma unroll
    for (int off = 1; off < 1024; off <<= 1) {
        int t = (threadIdx.x >= off) ? sh[threadIdx.x - off] : 0;
        __syncthreads();
        sh[threadIdx.x] += t;
        __syncthreads();
    }
    int agg = sh[1023];
    if (threadIdx.x >= 992) {
        int lane = threadIdx.x - 992;
        if (bid == 0) {
            if (lane == 0) {
                g_pre[0] = agg;
                __threadfence();
                g_flag[0] = 2;
                s_excl = 0;
            }
        } else {
            if (lane == 0) {
                g_agg[bid] = agg;
                __threadfence();
                g_flag[bid] = 1;
            }
            __syncwarp();
            int excl = 0;
            int j = bid - 1;
            while (true) {
                int idx = j - lane;
                int f = 0, val = 0;
                if (idx >= 0) {
                    do { f = g_flag[idx]; } while (f == 0);
                    __threadfence();
                    val = (f == 2) ? g_pre[idx] : g_agg[idx];
                }
                unsigned pm = __ballot_sync(0xffffffff, (idx >= 0) && (f == 2));
                int stop = __ffs(pm) - 1;
                int take = (idx >= 0) && (stop < 0 || lane <= stop);
                int contrib = take ? val : 0;
                #pragma unroll
                for (int o = 16; o; o >>= 1)
                    contrib += __shfl_down_sync(0xffffffff, contrib, o);
                excl += __shfl_sync(0xffffffff, contrib, 0);
                if (stop >= 0) break;
                j -= 32;
            }
            if (lane == 0) {
                g_pre[bid] = excl + agg;
                __threadfence();
                g_flag[bid] = 2;
                s_excl = excl;
            }
        }
    }
    __syncthreads();
    int base = (bid == 0) ? 0 : s_excl;
    if (i < NN) {
        int excl_i = sh[threadIdx.x] - v + base;
        g_rowptr[i] = excl_i;
        g_cursor[i] = excl_i;
        if (i == NN - 1) g_rowptr[NN] = sh[threadIdx.x] + base;
    }
}

// scatter: 4 edges/thread for MLP against ATOMG latency
__global__ void k_scatter(const int* __restrict__ src, const int* __restrict__ dst,
                          const float* __restrict__ nrm) {
    int e4 = blockIdx.x * blockDim.x + threadIdx.x;
    if (e4 < NE / 4) {
        int4   d = ((const int4*)dst)[e4];
        int4   s = ((const int4*)src)[e4];
        float4 w = ((const float4*)nrm)[e4];
        int p0 = atomicAdd(&g_cursor[d.x], 1);
        int p1 = atomicAdd(&g_cursor[d.y], 1);
        int p2 = atomicAdd(&g_cursor[d.z], 1);
        int p3 = atomicAdd(&g_cursor[d.w], 1);
        g_edge[p0] = make_int2(s.x, __float_as_int(w.x));
        g_edge[p1] = make_int2(s.y, __float_as_int(w.y));
        g_edge[p2] = make_int2(s.z, __float_as_int(w.z));
        g_edge[p3] = make_int2(s.w, __float_as_int(w.w));
    }
}

// ---------------- K-hop propagation: warp per dst, fp16 rows, fp32 accum (unroll-2) ----------------
__global__ void k_prop(int par) {
    int gt = blockIdx.x * blockDim.x + threadIdx.x;
    int node = gt >> 5;
    int lane = gt & 31;
    if (node >= NN) return;
    const uint2* in2  = (const uint2*)(par ? g_fh0 : g_fh1);
    uint2*       out2 = (uint2*)(par ? g_fh1 : g_fh0);
    int beg = g_rowptr[node];
    int end = g_rowptr[node + 1];
    float4 acc = make_float4(0.f, 0.f, 0.f, 0.f);
    int j = beg;
    for (; j + 2 <= end; j += 2) {
        int2 e0 = g_edge[j];
        int2 e1 = g_edge[j + 1];
        uint2 v0 = in2[(long)e0.x * 32 + lane];
        uint2 v1 = in2[(long)e1.x * 32 + lane];
        float w0 = __int_as_float(e0.y), w1 = __int_as_float(e1.y);
        float2 a0 = __half22float2(*(__half2*)&v0.x);
        float2 a1 = __half22float2(*(__half2*)&v0.y);
        float2 b0 = __half22float2(*(__half2*)&v1.x);
        float2 b1 = __half22float2(*(__half2*)&v1.y);
        acc.x = fmaf(a0.x, w0, fmaf(b0.x, w1, acc.x));
        acc.y = fmaf(a0.y, w0, fmaf(b0.y, w1, acc.y));
        acc.z = fmaf(a1.x, w0, fmaf(b1.x, w1, acc.z));
        acc.w = fmaf(a1.y, w0, fmaf(b1.y, w1, acc.w));
    }
    if (j < end) {
        int2 e0 = g_edge[j];
        uint2 v0 = in2[(long)e0.x * 32 + lane];
        float w0 = __int_as_float(e0.y);
        float2 a0 = __half22float2(*(__half2*)&v0.x);
        float2 a1 = __half22float2(*(__half2*)&v0.y);
        acc.x = fmaf(a0.x, w0, acc.x);
        acc.y = fmaf(a0.y, w0, acc.y);
        acc.z = fmaf(a1.x, w0, acc.z);
        acc.w = fmaf(a1.y, w0, acc.w);
    }
    uint2 o;
    *(__half2*)&o.x = __float22half2_rn(make_float2(acc.x, acc.y));
    *(__half2*)&o.y = __float22half2_rn(make_float2(acc.z, acc.w));
    out2[node * 32 + lane] = o;
}

// ---------------- GEMM1 (fp16 MMA + ldmatrix): h = ft @ W1^T + b1 + BN stats ----------------
#define S1 40   // smem stride in halves: 80B rows -> LDSM phases conflict-free
__global__ __launch_bounds__(256) void k_gemm1(const float* __restrict__ bias) {
    __shared__ __half As[128 * S1];
    __shared__ __half Bs[128 * S1];
    __shared__ float s_bias[128];
    const int tid = threadIdx.x;
    const int m0 = blockIdx.x * 128, n0 = blockIdx.y * 128;
    const int wid = tid >> 5, lane = tid & 31;
    const int g = lane >> 2, t = lane & 3;
    const int wm = (wid & 1) * 64, wn = (wid >> 1) * 32;
    if (tid < 128) s_bias[tid] = bias[n0 + tid];

    float acc[4][4][4];
    #pragma unroll
    for (int i = 0; i < 4; i++)
        #pragma unroll
        for (int j = 0; j < 4; j++)
            #pragma unroll
            for (int r = 0; r < 4; r++) acc[i][j][r] = 0.f;

    const unsigned asb = (unsigned)__cvta_generic_to_shared(As);
    const unsigned bsb = (unsigned)__cvta_generic_to_shared(Bs);
    const unsigned aBase = asb + (((wm + (lane & 15)) * S1 + (lane >> 4) * 8) << 1);
    const unsigned bBase = bsb + (((wn + (lane & 7)) * S1 + ((lane >> 3) & 1) * 8) << 1);

    const int lrow = tid >> 1, lkq = (tid & 1) * 16;
    int gr = m0 + lrow; if (gr >= NN) gr = NN - 1;
    const __half* aptr = &g_fh0[gr * FD + lkq];
    const __half* bptr = &g_w1h[(n0 + lrow) * FD + lkq];

    uint4 ra0 = *(const uint4*)(aptr);
    uint4 ra1 = *(const uint4*)(aptr + 8);
    uint4 rb0 = *(const uint4*)(bptr);
    uint4 rb1 = *(const uint4*)(bptr + 8);
    *(uint4*)&As[lrow * S1 + lkq]     = ra0;
    *(uint4*)&As[lrow * S1 + lkq + 8] = ra1;
    *(uint4*)&Bs[lrow * S1 + lkq]     = rb0;
    *(uint4*)&Bs[lrow * S1 + lkq + 8] = rb1;
    __syncthreads();

    for (int kt = 0; kt < FD; kt += 32) {
        bool more = (kt + 32 < FD);
        if (more) {
            ra0 = *(const uint4*)(aptr + kt + 32);
            ra1 = *(const uint4*)(aptr + kt + 40);
            rb0 = *(const uint4*)(bptr + kt + 32);
            rb1 = *(const uint4*)(bptr + kt + 40);
        }
        #pragma unroll
        for (int ks = 0; ks < 32; ks += 16) {
            unsigned bf[4][2];
            #pragma unroll
            for (int j = 0; j < 4; j++)
                ldsm_x2(bf[j], bBase + ((j * 8 * S1 + ks) << 1));
            #pragma unroll
            for (int i = 0; i < 4; i++) {
                unsigned af[4];
                ldsm_x4(af, aBase + ((i * 16 * S1 + ks) << 1));
                #pragma unroll
                for (int j = 0; j < 4; j++) mma_f16(acc[i][j], af, bf[j]);
            }
        }
        __syncthreads();
        if (more) {
            *(uint4*)&As[lrow * S1 + lkq]     = ra0;
            *(uint4*)&As[lrow * S1 + lkq + 8] = ra1;
            *(uint4*)&Bs[lrow * S1 + lkq]     = rb0;
            *(uint4*)&Bs[lrow * S1 + lkq + 8] = rb1;
            __syncthreads();
        }
    }

    // Epilogue: bias, write h (fp16), fused BN partials -> slotted atomics
    float s0[4] = {0.f,0.f,0.f,0.f}, q0[4] = {0.f,0.f,0.f,0.f};
    float s1[4] = {0.f,0.f,0.f,0.f}, q1[4] = {0.f,0.f,0.f,0.f};
    #pragma unroll
    for (int i = 0; i < 4; i++) {
        int r0 = m0 + wm + 16 * i + g;
        int r1 = r0 + 8;
        #pragma unroll
        for (int j = 0; j < 4; j++) {
            int lc = wn + 8 * j + 2 * t;
            float b0v = s_bias[lc], b1v = s_bias[lc + 1];
            float h00 = acc[i][j][0] + b0v, h01 = acc[i][j][1] + b1v;
            float h10 = acc[i][j][2] + b0v, h11 = acc[i][j][3] + b1v;
            if (r0 < NN) {
                *(__half2*)&g_hh[r0 * NH + n0 + lc] = __float22half2_rn(make_float2(h00, h01));
                s0[j] += h00; q0[j] = fmaf(h00, h00, q0[j]);
                s1[j] += h01; q1[j] = fmaf(h01, h01, q1[j]);
            }
            if (r1 < NN) {
                *(__half2*)&g_hh[r1 * NH + n0 + lc] = __float22half2_rn(make_float2(h10, h11));
                s0[j] += h10; q0[j] = fmaf(h10, h10, q0[j]);
                s1[j] += h11; q1[j] = fmaf(h11, h11, q1[j]);
            }
        }
    }
    #pragma unroll
    for (int j = 0; j < 4; j++) {
        #pragma unroll
        for (int off = 4; off < 32; off <<= 1) {
            s0[j] += __shfl_xor_sync(0xffffffff, s0[j], off);
            q0[j] += __shfl_xor_sync(0xffffffff, q0[j], off);
            s1[j] += __shfl_xor_sync(0xffffffff, s1[j], off);
            q1[j] += __shfl_xor_sync(0xffffffff, q1[j], off);
        }
    }
    if (lane < 4) {
        int slot = ((blockIdx.x ^ wid) & (NSLOT - 1)) * NH;
        #pragma unroll
        for (int j = 0; j < 4; j++) {
            int col = n0 + wn + 8 * j + 2 * lane;
            atomicAdd(&g_colsum[slot + col],     s0[j]);
            atomicAdd(&g_colsum[slot + col + 1], s1[j]);
            atomicAdd(&g_colsq[slot + col],      q0[j]);
            atomicAdd(&g_colsq[slot + col + 1],  q1[j]);
        }
    }
}

// ---------------- GEMM2 (fp16 MMA + ldmatrix): out = relu(h*sc+sh) @ W2^T + b2 ----------------
__global__ __launch_bounds__(256) void k_gemm2(const float* __restrict__ gamma,
                                               const float* __restrict__ beta,
                                               const float* __restrict__ b2,
                                               float* __restrict__ out) {
    __shared__ __half As[128 * S1];
    __shared__ __half Bs[64 * S1];
    __shared__ float s_scale[NH];
    __shared__ float s_shift[NH];
    __shared__ float s_b2[NC];
    const int tid = threadIdx.x;
    const int m0 = blockIdx.x * 128;
    const int wid = tid >> 5, lane = tid & 31;
    const int g = lane >> 2, t = lane & 3;
    const int wm = (wid & 3) * 32, wn = (wid >> 2) * 32;
    // BN finalize from slotted partials (redundant per block)
    for (int i = tid; i < NH; i += 256) {
        float s = 0.f, q = 0.f;
        #pragma unroll
        for (int r = 0; r < NSLOT; r++) { s += g_colsum[r * NH + i]; q += g_colsq[r * NH + i]; }
        float mean = s * (1.0f / NN);
        float var  = q * (1.0f / NN) - mean * mean;
        float sc = gamma[i] * rsqrtf(var + 1e-5f);
        s_scale[i] = sc;
        s_shift[i] = beta[i] - mean * sc;
    }
    if (tid < NC) s_b2[tid] = b2[tid];

    float acc[2][4][4];
    #pragma unroll
    for (int i = 0; i < 2; i++)
        #pragma unroll
        for (int j = 0; j < 4; j++)
            #pragma unroll
            for (int r = 0; r < 4; r++) acc[i][j][r] = 0.f;

    const unsigned asb = (unsigned)__cvta_generic_to_shared(As);
    const unsigned bsb = (unsigned)__cvta_generic_to_shared(Bs);
    const unsigned aBase = asb + (((wm + (lane & 15)) * S1 + (lane >> 4) * 8) << 1);
    const unsigned bBase = bsb + (((wn + (lane & 7)) * S1 + ((lane >> 3) & 1) * 8) << 1);

    const int lrow = tid >> 1, lkq = (tid & 1) * 16;
    const int brow = tid >> 2, bkq = (tid & 3) * 8;
    int gr = m0 + lrow; if (gr >= NN) gr = NN - 1;
    const __half* aptr = &g_hh[gr * NH + lkq];
    const __half* bptr = &g_w2h[brow * NH + bkq];

    uint4 ra0 = *(const uint4*)(aptr);
    uint4 ra1 = *(const uint4*)(aptr + 8);
    uint4 rb0 = *(const uint4*)(bptr);
    __syncthreads();   // s_scale/s_shift ready

    {
        unsigned res[8];
        const unsigned* vp = (const unsigned*)&ra0;
        #pragma unroll
        for (int p = 0; p < 4; p++) {
            int k = lkq + p * 2;
            float2 f = __half22float2(*(__half2*)&vp[p]);
            f.x = fmaxf(fmaf(f.x, s_scale[k],     s_shift[k]),     0.f);
            f.y = fmaxf(fmaf(f.y, s_scale[k + 1], s_shift[k + 1]), 0.f);
            __half2 h = __float22half2_rn(f);
            res[p] = *(unsigned*)&h;
        }
        const unsigned* wq = (const unsigned*)&ra1;
        #pragma unroll
        for (int p = 0; p < 4; p++) {
            int k = lkq + 8 + p * 2;
            float2 f = __half22float2(*(__half2*)&wq[p]);
            f.x = fmaxf(fmaf(f.x, s_scale[k],     s_shift[k]),     0.f);
            f.y = fmaxf(fmaf(f.y, s_scale[k + 1], s_shift[k + 1]), 0.f);
            __half2 h = __float22half2_rn(f);
            res[p + 4] = *(unsigned*)&h;
        }
        *(uint4*)&As[lrow * S1 + lkq]     = *(uint4*)&res[0];
        *(uint4*)&As[lrow * S1 + lkq + 8] = *(uint4*)&res[4];
        *(uint4*)&Bs[brow * S1 + bkq] = rb0;
    }
    __syncthreads();

    for (int kt = 0; kt < NH; kt += 32) {
        bool more = (kt + 32 < NH);
        if (more) {
            ra0 = *(const uint4*)(aptr + kt + 32);
            ra1 = *(const uint4*)(aptr + kt + 40);
            rb0 = *(const uint4*)(bptr + kt + 32);
        }
        #pragma unroll
        for (int ks = 0; ks < 32; ks += 16) {
            unsigned bf[4][2];
            #pragma unroll
            for (int j = 0; j < 4; j++)
                ldsm_x2(bf[j], bBase + ((j * 8 * S1 + ks) << 1));
            #pragma unroll
            for (int i = 0; i < 2; i++) {
                unsigned af[4];
                ldsm_x4(af, aBase + ((i * 16 * S1 + ks) << 1));
                #pragma unroll
                for (int j = 0; j < 4; j++) mma_f16(acc[i][j], af, bf[j]);
            }
        }
        __syncthreads();
        if (more) {
            int kb = kt + 32;
            unsigned res[8];
            const unsigned* vp = (const unsigned*)&ra0;
            #pragma unroll
            for (int p = 0; p < 4; p++) {
                int k = kb + lkq + p * 2;
                float2 f = __half22float2(*(__half2*)&vp[p]);
                f.x = fmaxf(fmaf(f.x, s_scale[k],     s_shift[k]),     0.f);
                f.y = fmaxf(fmaf(f.y, s_scale[k + 1], s_shift[k + 1]), 0.f);
                __half2 h = __float22half2_rn(f);
                res[p] = *(unsigned*)&h;
            }
            const unsigned* wq = (const unsigned*)&ra1;
            #pragma unroll
            for (int p = 0; p < 4; p++) {
                int k = kb + lkq + 8 + p * 2;
                float2 f = __half22float2(*(__half2*)&wq[p]);
                f.x = fmaxf(fmaf(f.x, s_scale[k],     s_shift[k]),     0.f);
                f.y = fmaxf(fmaf(f.y, s_scale[k + 1], s_shift[k + 1]), 0.f);
                __half2 h = __float22half2_rn(f);
                res[p + 4] = *(unsigned*)&h;
            }
            *(uint4*)&As[lrow * S1 + lkq]     = *(uint4*)&res[0];
            *(uint4*)&As[lrow * S1 + lkq + 8] = *(uint4*)&res[4];
            *(uint4*)&Bs[brow * S1 + bkq] = rb0;
            __syncthreads();
        }
    }
    #pragma unroll
    for (int i = 0; i < 2; i++) {
        int r0 = m0 + wm + 16 * i + g;
        int r1 = r0 + 8;
        #pragma unroll
        for (int j = 0; j < 4; j++) {
            int col = wn + 8 * j + 2 * t;
            float b0v = s_b2[col], b1v = s_b2[col + 1];
            if (r0 < NN)
                *(float2*)&out[r0 * NC + col] = make_float2(acc[i][j][0] + b0v, acc[i][j][1] + b1v);
            if (r1 < NN)
                *(float2*)&out[r1 * NC + col] = make_float2(acc[i][j][2] + b0v, acc[i][j][3] + b1v);
        }
    }
}

// ---------------- host launch ----------------
extern "C" void kernel_launch(void* const* d_in, const int* in_sizes, int n_in,
                              void* d_out, int out_size) {
    const float* feat   = (const float*)d_in[0];
    const int*   src    = (const int*)d_in[1];
    const int*   dst    = (const int*)d_in[2];
    const float* nrm    = (const float*)d_in[3];
    const float* fc1_w  = (const float*)d_in[4];
    const float* fc1_b  = (const float*)d_in[5];
    const float* gamma  = (const float*)d_in[6];
    const float* beta   = (const float*)d_in[7];
    const float* fc2_w  = (const float*)d_in[8];
    const float* fc2_b  = (const float*)d_in[9];
    float* out = (float*)d_out;

    k_cvt<<<(NN * FD / 2 + 255) / 256, 256>>>(feat, fc1_w, fc2_w, dst);
    k_hist<<<(NE / 4 + 255) / 256, 256>>>(dst);
    k_scan<<<SCAN_BLOCKS, 1024>>>();
    k_scatter<<<(NE / 4 + 255) / 256, 256>>>(src, dst, nrm);

    int prop_blocks = (NN * 32 + 255) / 256;
    k_prop<<<prop_blocks, 256>>>(0);
    k_prop<<<prop_blocks, 256>>>(1);
    k_prop<<<prop_blocks, 256>>>(0);

    dim3 g1((NN + 127) / 128, NH / 128);
    k_gemm1<<<g1, 256>>>(fc1_b);
    k_gemm2<<<(NN + 127) / 128, 256>>>(gamma, beta, fc2_b, out);
}

// round 11
// speedup vs baseline: 1.0307x; 1.0115x over previous
#include <cuda_runtime.h>
#include <cuda_fp16.h>

#define NN 100000
#define NE 1600000
#define FD 128
#define NH 512
#define NC 64
#define SCAN_BLOCKS 98   // ceil(100000/1024)
#define NSLOT 8

// ---------------- device scratch ----------------
__device__ int    g_deg[NN + 1];
__device__ int    g_rowptr[NN + 1];
__device__ int    g_rank[NE];       // per-edge rank within dst bucket (from hist atomics)
__device__ int2   g_edge[NE];       // (src, wgt bits) interleaved
__device__ __half g_fh0[NN * FD];
__device__ __half g_fh1[NN * FD];
__device__ __half g_hh[NN * NH];
__device__ __half g_w1h[NH * FD];   // fc1_w as fp16
__device__ __half g_w2h[NC * NH];   // fc2_w as fp16
__device__ float  g_colsum[NSLOT * NH];
__device__ float  g_colsq[NSLOT * NH];
// decoupled-lookback scan state
__device__ volatile int g_flag[SCAN_BLOCKS];
__device__ volatile int g_agg[SCAN_BLOCKS];
__device__ volatile int g_pre[SCAN_BLOCKS];

// ---------------- mma / ldmatrix helpers ----------------
__device__ __forceinline__ void mma_f16(float* c, const unsigned* a, const unsigned* b) {
    asm volatile(
        "mma.sync.aligned.m16n8k16.row.col.f32.f16.f16.f32 "
        "{%0,%1,%2,%3}, {%4,%5,%6,%7}, {%8,%9}, {%0,%1,%2,%3};"
        : "+f"(c[0]), "+f"(c[1]), "+f"(c[2]), "+f"(c[3])
        : "r"(a[0]), "r"(a[1]), "r"(a[2]), "r"(a[3]), "r"(b[0]), "r"(b[1]));
}

__device__ __forceinline__ void ldsm_x4(unsigned* r, unsigned addr) {
    asm volatile("ldmatrix.sync.aligned.m8n8.x4.shared.b16 {%0,%1,%2,%3}, [%4];"
                 : "=r"(r[0]), "=r"(r[1]), "=r"(r[2]), "=r"(r[3]) : "r"(addr));
}

__device__ __forceinline__ void ldsm_x2(unsigned* r, unsigned addr) {
    asm volatile("ldmatrix.sync.aligned.m8n8.x2.shared.b16 {%0,%1}, [%2];"
                 : "=r"(r[0]), "=r"(r[1]) : "r"(addr));
}

// ---------------- cvt + zero ----------------
__global__ void k_cvt(const float* __restrict__ feat,
                      const float* __restrict__ w1,
                      const float* __restrict__ w2) {
    int i = blockIdx.x * blockDim.x + threadIdx.x;
    if (i < NN * FD / 2) {
        float2 v = ((const float2*)feat)[i];
        ((__half2*)g_fh1)[i] = __float22half2_rn(v);
    }
    if (i < NH * FD / 2) {
        float2 v = ((const float2*)w1)[i];
        ((__half2*)g_w1h)[i] = __float22half2_rn(v);
    }
    if (i < NC * NH / 2) {
        float2 v = ((const float2*)w2)[i];
        ((__half2*)g_w2h)[i] = __float22half2_rn(v);
    }
    if (i < NN + 1) g_deg[i] = 0;
    if (i < NSLOT * NH) { g_colsum[i] = 0.f; g_colsq[i] = 0.f; }
    if (i < SCAN_BLOCKS) g_flag[i] = 0;
}

// ---------------- hist: count degrees AND record per-edge rank ----------------
__global__ void k_hist(const int* __restrict__ dst) {
    int e4 = blockIdx.x * blockDim.x + threadIdx.x;
    if (e4 < NE / 4) {
        int4 d = ((const int4*)dst)[e4];
        int4 r;
        r.x = atomicAdd(&g_deg[d.x], 1);
        r.y = atomicAdd(&g_deg[d.y], 1);
        r.z = atomicAdd(&g_deg[d.z], 1);
        r.w = atomicAdd(&g_deg[d.w], 1);
        ((int4*)g_rank)[e4] = r;
    }
}

// single-pass scan with warp-parallel decoupled lookback (98 blocks all resident)
__global__ void k_scan() {
    __shared__ int sh[1024];
    __shared__ int s_excl;
    const int bid = blockIdx.x;
    int i = bid * 1024 + threadIdx.x;
    int v = (i < NN) ? g_deg[i] : 0;
    sh[threadIdx.x] = v;
    __syncthreads();
    #pragma unroll
    for (int off = 1; off < 1024; off <<= 1) {
        int t = (threadIdx.x >= off) ? sh[threadIdx.x - off] : 0;
        __syncthreads();
        sh[threadIdx.x] += t;
        __syncthreads();
    }
    int agg = sh[1023];
    if (threadIdx.x >= 992) {
        int lane = threadIdx.x - 992;
        if (bid == 0) {
            if (lane == 0) {
                g_pre[0] = agg;
                __threadfence();
                g_flag[0] = 2;
                s_excl = 0;
            }
        } else {
            if (lane == 0) {
                g_agg[bid] = agg;
                __threadfence();
                g_flag[bid] = 1;
            }
            __syncwarp();
            int excl = 0;
            int j = bid - 1;
            while (true) {
                int idx = j - lane;
                int f = 0, val = 0;
                if (idx >= 0) {
                    do { f = g_flag[idx]; } while (f == 0);
                    __threadfence();
                    val = (f == 2) ? g_pre[idx] : g_agg[idx];
                }
                unsigned pm = __ballot_sync(0xffffffff, (idx >= 0) && (f == 2));
                int stop = __ffs(pm) - 1;
                int take = (idx >= 0) && (stop < 0 || lane <= stop);
                int contrib = take ? val : 0;
                #pragma unroll
                for (int o = 16; o; o >>= 1)
                    contrib += __shfl_down_sync(0xffffffff, contrib, o);
                excl += __shfl_sync(0xffffffff, contrib, 0);
                if (stop >= 0) break;
                j -= 32;
            }
            if (lane == 0) {
                g_pre[bid] = excl + agg;
                __threadfence();
                g_flag[bid] = 2;
                s_excl = excl;
            }
        }
    }
    __syncthreads();
    int base = (bid == 0) ? 0 : s_excl;
    if (i < NN) {
        int excl_i = sh[threadIdx.x] - v + base;
        g_rowptr[i] = excl_i;
        if (i == NN - 1) g_rowptr[NN] = sh[threadIdx.x] + base;
    }
}

// scatter: NO atomics — pos = rowptr[dst] + rank (rank recorded by hist)
__global__ void k_scatter(const int* __restrict__ src, const int* __restrict__ dst,
                          const float* __restrict__ nrm) {
    int e4 = blockIdx.x * blockDim.x + threadIdx.x;
    if (e4 < NE / 4) {
        int4   d = ((const int4*)dst)[e4];
        int4   s = ((const int4*)src)[e4];
        float4 w = ((const float4*)nrm)[e4];
        int4   r = ((const int4*)g_rank)[e4];
        g_edge[g_rowptr[d.x] + r.x] = make_int2(s.x, __float_as_int(w.x));
        g_edge[g_rowptr[d.y] + r.y] = make_int2(s.y, __float_as_int(w.y));
        g_edge[g_rowptr[d.z] + r.z] = make_int2(s.z, __float_as_int(w.z));
        g_edge[g_rowptr[d.w] + r.w] = make_int2(s.w, __float_as_int(w.w));
    }
}

// ---------------- K-hop propagation: warp per dst, fp16 rows, fp32 accum (unroll-2) ----------------
__global__ void k_prop(int par) {
    int gt = blockIdx.x * blockDim.x + threadIdx.x;
    int node = gt >> 5;
    int lane = gt & 31;
    if (node >= NN) return;
    const uint2* in2  = (const uint2*)(par ? g_fh0 : g_fh1);
    uint2*       out2 = (uint2*)(par ? g_fh1 : g_fh0);
    int beg = g_rowptr[node];
    int end = g_rowptr[node + 1];
    float4 acc = make_float4(0.f, 0.f, 0.f, 0.f);
    int j = beg;
    for (; j + 2 <= end; j += 2) {
        int2 e0 = g_edge[j];
        int2 e1 = g_edge[j + 1];
        uint2 v0 = in2[(long)e0.x * 32 + lane];
        uint2 v1 = in2[(long)e1.x * 32 + lane];
        float w0 = __int_as_float(e0.y), w1 = __int_as_float(e1.y);
        float2 a0 = __half22float2(*(__half2*)&v0.x);
        float2 a1 = __half22float2(*(__half2*)&v0.y);
        float2 b0 = __half22float2(*(__half2*)&v1.x);
        float2 b1 = __half22float2(*(__half2*)&v1.y);
        acc.x = fmaf(a0.x, w0, fmaf(b0.x, w1, acc.x));
        acc.y = fmaf(a0.y, w0, fmaf(b0.y, w1, acc.y));
        acc.z = fmaf(a1.x, w0, fmaf(b1.x, w1, acc.z));
        acc.w = fmaf(a1.y, w0, fmaf(b1.y, w1, acc.w));
    }
    if (j < end) {
        int2 e0 = g_edge[j];
        uint2 v0 = in2[(long)e0.x * 32 + lane];
        float w0 = __int_as_float(e0.y);
        float2 a0 = __half22float2(*(__half2*)&v0.x);
        float2 a1 = __half22float2(*(__half2*)&v0.y);
        acc.x = fmaf(a0.x, w0, acc.x);
        acc.y = fmaf(a0.y, w0, acc.y);
        acc.z = fmaf(a1.x, w0, acc.z);
        acc.w = fmaf(a1.y, w0, acc.w);
    }
    uint2 o;
    *(__half2*)&o.x = __float22half2_rn(make_float2(acc.x, acc.y));
    *(__half2*)&o.y = __float22half2_rn(make_float2(acc.z, acc.w));
    out2[node * 32 + lane] = o;
}

// ---------------- GEMM1 (fp16 MMA + ldmatrix): h = ft @ W1^T + b1 + BN stats ----------------
#define S1 40   // smem stride in halves: 80B rows -> LDSM phases conflict-free
__global__ __launch_bounds__(256) void k_gemm1(const float* __restrict__ bias) {
    __shared__ __half As[128 * S1];
    __shared__ __half Bs[128 * S1];
    __shared__ float s_bias[128];
    const int tid = threadIdx.x;
    const int m0 = blockIdx.x * 128, n0 = blockIdx.y * 128;
    const int wid = tid >> 5, lane = tid & 31;
    const int g = lane >> 2, t = lane & 3;
    const int wm = (wid & 1) * 64, wn = (wid >> 1) * 32;
    if (tid < 128) s_bias[tid] = bias[n0 + tid];

    float acc[4][4][4];
    #pragma unroll
    for (int i = 0; i < 4; i++)
        #pragma unroll
        for (int j = 0; j < 4; j++)
            #pragma unroll
            for (int r = 0; r < 4; r++) acc[i][j][r] = 0.f;

    const unsigned asb = (unsigned)__cvta_generic_to_shared(As);
    const unsigned bsb = (unsigned)__cvta_generic_to_shared(Bs);
    const unsigned aBase = asb + (((wm + (lane & 15)) * S1 + (lane >> 4) * 8) << 1);
    const unsigned bBase = bsb + (((wn + (lane & 7)) * S1 + ((lane >> 3) & 1) * 8) << 1);

    const int lrow = tid >> 1, lkq = (tid & 1) * 16;
    int gr = m0 + lrow; if (gr >= NN) gr = NN - 1;
    const __half* aptr = &g_fh0[gr * FD + lkq];
    const __half* bptr = &g_w1h[(n0 + lrow) * FD + lkq];

    uint4 ra0 = *(const uint4*)(aptr);
    uint4 ra1 = *(const uint4*)(aptr + 8);
    uint4 rb0 = *(const uint4*)(bptr);
    uint4 rb1 = *(const uint4*)(bptr + 8);
    *(uint4*)&As[lrow * S1 + lkq]     = ra0;
    *(uint4*)&As[lrow * S1 + lkq + 8] = ra1;
    *(uint4*)&Bs[lrow * S1 + lkq]     = rb0;
    *(uint4*)&Bs[lrow * S1 + lkq + 8] = rb1;
    __syncthreads();

    for (int kt = 0; kt < FD; kt += 32) {
        bool more = (kt + 32 < FD);
        if (more) {
            ra0 = *(const uint4*)(aptr + kt + 32);
            ra1 = *(const uint4*)(aptr + kt + 40);
            rb0 = *(const uint4*)(bptr + kt + 32);
            rb1 = *(const uint4*)(bptr + kt + 40);
        }
        #pragma unroll
        for (int ks = 0; ks < 32; ks += 16) {
            unsigned bf[4][2];
            #pragma unroll
            for (int j = 0; j < 4; j++)
                ldsm_x2(bf[j], bBase + ((j * 8 * S1 + ks) << 1));
            #pragma unroll
            for (int i = 0; i < 4; i++) {
                unsigned af[4];
                ldsm_x4(af, aBase + ((i * 16 * S1 + ks) << 1));
                #pragma unroll
                for (int j = 0; j < 4; j++) mma_f16(acc[i][j], af, bf[j]);
            }
        }
        __syncthreads();
        if (more) {
            *(uint4*)&As[lrow * S1 + lkq]     = ra0;
            *(uint4*)&As[lrow * S1 + lkq + 8] = ra1;
            *(uint4*)&Bs[lrow * S1 + lkq]     = rb0;
            *(uint4*)&Bs[lrow * S1 + lkq + 8] = rb1;
            __syncthreads();
        }
    }

    // Epilogue: bias, write h (fp16), fused BN partials -> slotted atomics
    float s0[4] = {0.f,0.f,0.f,0.f}, q0[4] = {0.f,0.f,0.f,0.f};
    float s1[4] = {0.f,0.f,0.f,0.f}, q1[4] = {0.f,0.f,0.f,0.f};
    #pragma unroll
    for (int i = 0; i < 4; i++) {
        int r0 = m0 + wm + 16 * i + g;
        int r1 = r0 + 8;
        #pragma unroll
        for (int j = 0; j < 4; j++) {
            int lc = wn + 8 * j + 2 * t;
            float b0v = s_bias[lc], b1v = s_bias[lc + 1];
            float h00 = acc[i][j][0] + b0v, h01 = acc[i][j][1] + b1v;
            float h10 = acc[i][j][2] + b0v, h11 = acc[i][j][3] + b1v;
            if (r0 < NN) {
                *(__half2*)&g_hh[r0 * NH + n0 + lc] = __float22half2_rn(make_float2(h00, h01));
                s0[j] += h00; q0[j] = fmaf(h00, h00, q0[j]);
                s1[j] += h01; q1[j] = fmaf(h01, h01, q1[j]);
            }
            if (r1 < NN) {
                *(__half2*)&g_hh[r1 * NH + n0 + lc] = __float22half2_rn(make_float2(h10, h11));
                s0[j] += h10; q0[j] = fmaf(h10, h10, q0[j]);
                s1[j] += h11; q1[j] = fmaf(h11, h11, q1[j]);
            }
        }
    }
    #pragma unroll
    for (int j = 0; j < 4; j++) {
        #pragma unroll
        for (int off = 4; off < 32; off <<= 1) {
            s0[j] += __shfl_xor_sync(0xffffffff, s0[j], off);
            q0[j] += __shfl_xor_sync(0xffffffff, q0[j], off);
            s1[j] += __shfl_xor_sync(0xffffffff, s1[j], off);
            q1[j] += __shfl_xor_sync(0xffffffff, q1[j], off);
        }
    }
    if (lane < 4) {
        int slot = ((blockIdx.x ^ wid) & (NSLOT - 1)) * NH;
        #pragma unroll
        for (int j = 0; j < 4; j++) {
            int col = n0 + wn + 8 * j + 2 * lane;
            atomicAdd(&g_colsum[slot + col],     s0[j]);
            atomicAdd(&g_colsum[slot + col + 1], s1[j]);
            atomicAdd(&g_colsq[slot + col],      q0[j]);
            atomicAdd(&g_colsq[slot + col + 1],  q1[j]);
        }
    }
}

// ---------------- GEMM2 (fp16 MMA + ldmatrix): out = relu(h*sc+sh) @ W2^T + b2 ----------------
__global__ __launch_bounds__(256) void k_gemm2(const float* __restrict__ gamma,
                                               const float* __restrict__ beta,
                                               const float* __restrict__ b2,
                                               float* __restrict__ out) {
    __shared__ __half As[128 * S1];
    __shared__ __half Bs[64 * S1];
    __shared__ float s_scale[NH];
    __shared__ float s_shift[NH];
    __shared__ float s_b2[NC];
    const int tid = threadIdx.x;
    const int m0 = blockIdx.x * 128;
    const int wid = tid >> 5, lane = tid & 31;
    const int g = lane >> 2, t = lane & 3;
    const int wm = (wid & 3) * 32, wn = (wid >> 2) * 32;
    // BN finalize from slotted partials (redundant per block)
    for (int i = tid; i < NH; i += 256) {
        float s = 0.f, q = 0.f;
        #pragma unroll
        for (int r = 0; r < NSLOT; r++) { s += g_colsum[r * NH + i]; q += g_colsq[r * NH + i]; }
        float mean = s * (1.0f / NN);
        float var  = q * (1.0f / NN) - mean * mean;
        float sc = gamma[i] * rsqrtf(var + 1e-5f);
        s_scale[i] = sc;
        s_shift[i] = beta[i] - mean * sc;
    }
    if (tid < NC) s_b2[tid] = b2[tid];

    float acc[2][4][4];
    #pragma unroll
    for (int i = 0; i < 2; i++)
        #pragma unroll
        for (int j = 0; j < 4; j++)
            #pragma unroll
            for (int r = 0; r < 4; r++) acc[i][j][r] = 0.f;

    const unsigned asb = (unsigned)__cvta_generic_to_shared(As);
    const unsigned bsb = (unsigned)__cvta_generic_to_shared(Bs);
    const unsigned aBase = asb + (((wm + (lane & 15)) * S1 + (lane >> 4) * 8) << 1);
    const unsigned bBase = bsb + (((wn + (lane & 7)) * S1 + ((lane >> 3) & 1) * 8) << 1);

    const int lrow = tid >> 1, lkq = (tid & 1) * 16;
    const int brow = tid >> 2, bkq = (tid & 3) * 8;
    int gr = m0 + lrow; if (gr >= NN) gr = NN - 1;
    const __half* aptr = &g_hh[gr * NH + lkq];
    const __half* bptr = &g_w2h[brow * NH + bkq];

    uint4 ra0 = *(const uint4*)(aptr);
    uint4 ra1 = *(const uint4*)(aptr + 8);
    uint4 rb0 = *(const uint4*)(bptr);
    __syncthreads();   // s_scale/s_shift ready

    {
        unsigned res[8];
        const unsigned* vp = (const unsigned*)&ra0;
        #pragma unroll
        for (int p = 0; p < 4; p++) {
            int k = lkq + p * 2;
            float2 f = __half22float2(*(__half2*)&vp[p]);
            f.x = fmaxf(fmaf(f.x, s_scale[k],     s_shift[k]),     0.f);
            f.y = fmaxf(fmaf(f.y, s_scale[k + 1], s_shift[k + 1]), 0.f);
            __half2 h = __float22half2_rn(f);
            res[p] = *(unsigned*)&h;
        }
        const unsigned* wq = (const unsigned*)&ra1;
        #pragma unroll
        for (int p = 0; p < 4; p++) {
            int k = lkq + 8 + p * 2;
            float2 f = __half22float2(*(__half2*)&wq[p]);
            f.x = fmaxf(fmaf(f.x, s_scale[k],     s_shift[k]),     0.f);
            f.y = fmaxf(fmaf(f.y, s_scale[k + 1], s_shift[k + 1]), 0.f);
            __half2 h = __float22half2_rn(f);
            res[p + 4] = *(unsigned*)&h;
        }
        *(uint4*)&As[lrow * S1 + lkq]     = *(uint4*)&res[0];
        *(uint4*)&As[lrow * S1 + lkq + 8] = *(uint4*)&res[4];
        *(uint4*)&Bs[brow * S1 + bkq] = rb0;
    }
    __syncthreads();

    for (int kt = 0; kt < NH; kt += 32) {
        bool more = (kt + 32 < NH);
        if (more) {
            ra0 = *(const uint4*)(aptr + kt + 32);
            ra1 = *(const uint4*)(aptr + kt + 40);
            rb0 = *(const uint4*)(bptr + kt + 32);
        }
        #pragma unroll
        for (int ks = 0; ks < 32; ks += 16) {
            unsigned bf[4][2];
            #pragma unroll
            for (int j = 0; j < 4; j++)
                ldsm_x2(bf[j], bBase + ((j * 8 * S1 + ks) << 1));
            #pragma unroll
            for (int i = 0; i < 2; i++) {
                unsigned af[4];
                ldsm_x4(af, aBase + ((i * 16 * S1 + ks) << 1));
                #pragma unroll
                for (int j = 0; j < 4; j++) mma_f16(acc[i][j], af, bf[j]);
            }
        }
        __syncthreads();
        if (more) {
            int kb = kt + 32;
            unsigned res[8];
            const unsigned* vp = (const unsigned*)&ra0;
            #pragma unroll
            for (int p = 0; p < 4; p++) {
                int k = kb + lkq + p * 2;
                float2 f = __half22float2(*(__half2*)&vp[p]);
                f.x = fmaxf(fmaf(f.x, s_scale[k],     s_shift[k]),     0.f);
                f.y = fmaxf(fmaf(f.y, s_scale[k + 1], s_shift[k + 1]), 0.f);
                __half2 h = __float22half2_rn(f);
                res[p] = *(unsigned*)&h;
            }
            const unsigned* wq = (const unsigned*)&ra1;
            #pragma unroll
            for (int p = 0; p < 4; p++) {
                int k = kb + lkq + 8 + p * 2;
                float2 f = __half22float2(*(__half2*)&wq[p]);
                f.x = fmaxf(fmaf(f.x, s_scale[k],     s_shift[k]),     0.f);
                f.y = fmaxf(fmaf(f.y, s_scale[k + 1], s_shift[k + 1]), 0.f);
                __half2 h = __float22half2_rn(f);
                res[p + 4] = *(unsigned*)&h;
            }
            *(uint4*)&As[lrow * S1 + lkq]     = *(uint4*)&res[0];
            *(uint4*)&As[lrow * S1 + lkq + 8] = *(uint4*)&res[4];
            *(uint4*)&Bs[brow * S1 + bkq] = rb0;
            __syncthreads();
        }
    }
    #pragma unroll
    for (int i = 0; i < 2; i++) {
        int r0 = m0 + wm + 16 * i + g;
        int r1 = r0 + 8;
        #pragma unroll
        for (int j = 0; j < 4; j++) {
            int col = wn + 8 * j + 2 * t;
            float b0v = s_b2[col], b1v = s_b2[col + 1];
            if (r0 < NN)
                *(float2*)&out[r0 * NC + col] = make_float2(acc[i][j][0] + b0v, acc[i][j][1] + b1v);
            if (r1 < NN)
                *(float2*)&out[r1 * NC + col] = make_float2(acc[i][j][2] + b0v, acc[i][j][3] + b1v);
        }
    }
}

// ---------------- host launch ----------------
extern "C" void kernel_launch(void* const* d_in, const int* in_sizes, int n_in,
                              void* d_out, int out_size) {
    const float* feat   = (const float*)d_in[0];
    const int*   src    = (const int*)d_in[1];
    const int*   dst    = (const int*)d_in[2];
    const float* nrm    = (const float*)d_in[3];
    const float* fc1_w  = (const float*)d_in[4];
    const float* fc1_b  = (const float*)d_in[5];
    const float* gamma  = (const float*)d_in[6];
    const float* beta   = (const float*)d_in[7];
    const float* fc2_w  = (const float*)d_in[8];
    const float* fc2_b  = (const float*)d_in[9];
    float* out = (float*)d_out;

    k_cvt<<<(NN * FD / 2 + 255) / 256, 256>>>(feat, fc1_w, fc2_w);
    k_hist<<<(NE / 4 + 255) / 256, 256>>>(dst);
    k_scan<<<SCAN_BLOCKS, 1024>>>();
    k_scatter<<<(NE / 4 + 255) / 256, 256>>>(src, dst, nrm);

    int prop_blocks = (NN * 32 + 255) / 256;
    k_prop<<<prop_blocks, 256>>>(0);
    k_prop<<<prop_blocks, 256>>>(1);
    k_prop<<<prop_blocks, 256>>>(0);

    dim3 g1((NN + 127) / 128, NH / 128);
    k_gemm1<<<g1, 256>>>(fc1_b);
    k_gemm2<<<(NN + 127) / 128, 256>>>(gamma, beta, fc2_b, out);
}

// round 12
// speedup vs baseline: 1.0390x; 1.0081x over previous
#include <cuda_runtime.h>
#include <cuda_fp16.h>

#define NN 100000
#define NE 1600000
#define FD 128
#define NH 512
#define NC 64
#define SCAN_BLOCKS 98   // ceil(100000/1024)
#define NSLOT 8

// ---------------- device scratch ----------------
// NOTE: g_deg and g_flag are zero on first use (CUDA zero-initializes device
// globals) and are re-zeroed at the END of k_scatter each replay, after their
// last reader. This keeps kernel_launch deterministic across graph replays.
__device__ int    g_deg[NN + 1];
__device__ int    g_rowptr[NN + 1];
__device__ int    g_rank[NE];       // per-edge rank within dst bucket (from hist atomics)
__device__ int2   g_edge[NE];       // (src, wgt bits) interleaved
__device__ __half g_fh0[NN * FD];
__device__ __half g_fh1[NN * FD];
__device__ __half g_hh[NN * NH];
__device__ __half g_w1h[NH * FD];   // fc1_w as fp16
__device__ __half g_w2h[NC * NH];   // fc2_w as fp16
__device__ float  g_colsum[NSLOT * NH];
__device__ float  g_colsq[NSLOT * NH];
// decoupled-lookback scan state
__device__ volatile int g_flag[SCAN_BLOCKS];
__device__ volatile int g_agg[SCAN_BLOCKS];
__device__ volatile int g_pre[SCAN_BLOCKS];

// ---------------- mma / ldmatrix helpers ----------------
__device__ __forceinline__ void mma_f16(float* c, const unsigned* a, const unsigned* b) {
    asm volatile(
        "mma.sync.aligned.m16n8k16.row.col.f32.f16.f16.f32 "
        "{%0,%1,%2,%3}, {%4,%5,%6,%7}, {%8,%9}, {%0,%1,%2,%3};"
        : "+f"(c[0]), "+f"(c[1]), "+f"(c[2]), "+f"(c[3])
        : "r"(a[0]), "r"(a[1]), "r"(a[2]), "r"(a[3]), "r"(b[0]), "r"(b[1]));
}

__device__ __forceinline__ void ldsm_x4(unsigned* r, unsigned addr) {
    asm volatile("ldmatrix.sync.aligned.m8n8.x4.shared.b16 {%0,%1,%2,%3}, [%4];"
                 : "=r"(r[0]), "=r"(r[1]), "=r"(r[2]), "=r"(r[3]) : "r"(addr));
}

__device__ __forceinline__ void ldsm_x2(unsigned* r, unsigned addr) {
    asm volatile("ldmatrix.sync.aligned.m8n8.x2.shared.b16 {%0,%1}, [%2];"
                 : "=r"(r[0]), "=r"(r[1]) : "r"(addr));
}

// ---------------- cvt + zero + hist (merged) ----------------
// g_deg is guaranteed zero at entry (zero-init on load; re-zeroed by k_scatter
// at the end of each previous replay), so hist atomics here are race-free.
__global__ void k_cvthist(const float* __restrict__ feat,
                          const float* __restrict__ w1,
                          const float* __restrict__ w2,
                          const int* __restrict__ dst) {
    int i = blockIdx.x * blockDim.x + threadIdx.x;
    if (i < NN * FD / 2) {
        float2 v = ((const float2*)feat)[i];
        ((__half2*)g_fh1)[i] = __float22half2_rn(v);
    }
    if (i < NH * FD / 2) {
        float2 v = ((const float2*)w1)[i];
        ((__half2*)g_w1h)[i] = __float22half2_rn(v);
    }
    if (i < NC * NH / 2) {
        float2 v = ((const float2*)w2)[i];
        ((__half2*)g_w2h)[i] = __float22half2_rn(v);
    }
    if (i < NSLOT * NH) { g_colsum[i] = 0.f; g_colsq[i] = 0.f; }
    if (i < NE / 4) {
        int4 d = ((const int4*)dst)[i];
        int4 r;
        r.x = atomicAdd(&g_deg[d.x], 1);
        r.y = atomicAdd(&g_deg[d.y], 1);
        r.z = atomicAdd(&g_deg[d.z], 1);
        r.w = atomicAdd(&g_deg[d.w], 1);
        ((int4*)g_rank)[i] = r;
    }
}

// single-pass scan with warp-parallel decoupled lookback (98 blocks all resident)
__global__ void k_scan() {
    __shared__ int sh[1024];
    __shared__ int s_excl;
    const int bid = blockIdx.x;
    int i = bid * 1024 + threadIdx.x;
    int v = (i < NN) ? g_deg[i] : 0;
    sh[threadIdx.x] = v;
    __syncthreads();
    #pragma unroll
    for (int off = 1; off < 1024; off <<= 1) {
        int t = (threadIdx.x >= off) ? sh[threadIdx.x - off] : 0;
        __syncthreads();
        sh[threadIdx.x] += t;
        __syncthreads();
    }
    int agg = sh[1023];
    if (threadIdx.x >= 992) {
        int lane = threadIdx.x - 992;
        if (bid == 0) {
            if (lane == 0) {
                g_pre[0] = agg;
                __threadfence();
                g_flag[0] = 2;
                s_excl = 0;
            }
        } else {
            if (lane == 0) {
                g_agg[bid] = agg;
                __threadfence();
                g_flag[bid] = 1;
            }
            __syncwarp();
            int excl = 0;
            int j = bid - 1;
            while (true) {
                int idx = j - lane;
                int f = 0, val = 0;
                if (idx >= 0) {
                    do { f = g_flag[idx]; } while (f == 0);
                    __threadfence();
                    val = (f == 2) ? g_pre[idx] : g_agg[idx];
                }
                unsigned pm = __ballot_sync(0xffffffff, (idx >= 0) && (f == 2));
                int stop = __ffs(pm) - 1;
                int take = (idx >= 0) && (stop < 0 || lane <= stop);
                int contrib = take ? val : 0;
                #pragma unroll
                for (int o = 16; o; o >>= 1)
                    contrib += __shfl_down_sync(0xffffffff, contrib, o);
                excl += __shfl_sync(0xffffffff, contrib, 0);
                if (stop >= 0) break;
                j -= 32;
            }
            if (lane == 0) {
                g_pre[bid] = excl + agg;
                __threadfence();
                g_flag[bid] = 2;
                s_excl = excl;
            }
        }
    }
    __syncthreads();
    int base = (bid == 0) ? 0 : s_excl;
    if (i < NN) {
        int excl_i = sh[threadIdx.x] - v + base;
        g_rowptr[i] = excl_i;
        if (i == NN - 1) g_rowptr[NN] = sh[threadIdx.x] + base;
    }
}

// scatter: NO atomics — pos = rowptr[dst] + rank; also re-zeroes deg/flag
// for the next replay (their last readers ran in k_scan this replay).
__global__ void k_scatter(const int* __restrict__ src, const int* __restrict__ dst,
                          const float* __restrict__ nrm) {
    int e4 = blockIdx.x * blockDim.x + threadIdx.x;
    if (e4 < NE / 4) {
        int4   d = ((const int4*)dst)[e4];
        int4   s = ((const int4*)src)[e4];
        float4 w = ((const float4*)nrm)[e4];
        int4   r = ((const int4*)g_rank)[e4];
        g_edge[g_rowptr[d.x] + r.x] = make_int2(s.x, __float_as_int(w.x));
        g_edge[g_rowptr[d.y] + r.y] = make_int2(s.y, __float_as_int(w.y));
        g_edge[g_rowptr[d.z] + r.z] = make_int2(s.z, __float_as_int(w.z));
        g_edge[g_rowptr[d.w] + r.w] = make_int2(s.w, __float_as_int(w.w));
    }
    if (e4 < NN + 1) g_deg[e4] = 0;
    if (e4 < SCAN_BLOCKS) g_flag[e4] = 0;
}

// ---------------- K-hop propagation: warp per dst, fp16 rows, fp32 accum (unroll-2) ----------------
__global__ void k_prop(int par) {
    int gt = blockIdx.x * blockDim.x + threadIdx.x;
    int node = gt >> 5;
    int lane = gt & 31;
    if (node >= NN) return;
    const uint2* in2  = (const uint2*)(par ? g_fh0 : g_fh1);
    uint2*       out2 = (uint2*)(par ? g_fh1 : g_fh0);
    int beg = g_rowptr[node];
    int end = g_rowptr[node + 1];
    float4 acc = make_float4(0.f, 0.f, 0.f, 0.f);
    int j = beg;
    for (; j + 2 <= end; j += 2) {
        int2 e0 = g_edge[j];
        int2 e1 = g_edge[j + 1];
        uint2 v0 = in2[(long)e0.x * 32 + lane];
        uint2 v1 = in2[(long)e1.x * 32 + lane];
        float w0 = __int_as_float(e0.y), w1 = __int_as_float(e1.y);
        float2 a0 = __half22float2(*(__half2*)&v0.x);
        float2 a1 = __half22float2(*(__half2*)&v0.y);
        float2 b0 = __half22float2(*(__half2*)&v1.x);
        float2 b1 = __half22float2(*(__half2*)&v1.y);
        acc.x = fmaf(a0.x, w0, fmaf(b0.x, w1, acc.x));
        acc.y = fmaf(a0.y, w0, fmaf(b0.y, w1, acc.y));
        acc.z = fmaf(a1.x, w0, fmaf(b1.x, w1, acc.z));
        acc.w = fmaf(a1.y, w0, fmaf(b1.y, w1, acc.w));
    }
    if (j < end) {
        int2 e0 = g_edge[j];
        uint2 v0 = in2[(long)e0.x * 32 + lane];
        float w0 = __int_as_float(e0.y);
        float2 a0 = __half22float2(*(__half2*)&v0.x);
        float2 a1 = __half22float2(*(__half2*)&v0.y);
        acc.x = fmaf(a0.x, w0, acc.x);
        acc.y = fmaf(a0.y, w0, acc.y);
        acc.z = fmaf(a1.x, w0, acc.z);
        acc.w = fmaf(a1.y, w0, acc.w);
    }
    uint2 o;
    *(__half2*)&o.x = __float22half2_rn(make_float2(acc.x, acc.y));
    *(__half2*)&o.y = __float22half2_rn(make_float2(acc.z, acc.w));
    out2[node * 32 + lane] = o;
}

// ---------------- GEMM1 (fp16 MMA + ldmatrix): h = ft @ W1^T + b1 + BN stats ----------------
#define S1 40   // smem stride in halves: 80B rows -> LDSM phases conflict-free
__global__ __launch_bounds__(256) void k_gemm1(const float* __restrict__ bias) {
    __shared__ __half As[128 * S1];
    __shared__ __half Bs[128 * S1];
    __shared__ float s_bias[128];
    const int tid = threadIdx.x;
    const int m0 = blockIdx.x * 128, n0 = blockIdx.y * 128;
    const int wid = tid >> 5, lane = tid & 31;
    const int g = lane >> 2, t = lane & 3;
    const int wm = (wid & 1) * 64, wn = (wid >> 1) * 32;
    if (tid < 128) s_bias[tid] = bias[n0 + tid];

    float acc[4][4][4];
    #pragma unroll
    for (int i = 0; i < 4; i++)
        #pragma unroll
        for (int j = 0; j < 4; j++)
            #pragma unroll
            for (int r = 0; r < 4; r++) acc[i][j][r] = 0.f;

    const unsigned asb = (unsigned)__cvta_generic_to_shared(As);
    const unsigned bsb = (unsigned)__cvta_generic_to_shared(Bs);
    const unsigned aBase = asb + (((wm + (lane & 15)) * S1 + (lane >> 4) * 8) << 1);
    const unsigned bBase = bsb + (((wn + (lane & 7)) * S1 + ((lane >> 3) & 1) * 8) << 1);

    const int lrow = tid >> 1, lkq = (tid & 1) * 16;
    int gr = m0 + lrow; if (gr >= NN) gr = NN - 1;
    const __half* aptr = &g_fh0[gr * FD + lkq];
    const __half* bptr = &g_w1h[(n0 + lrow) * FD + lkq];

    uint4 ra0 = *(const uint4*)(aptr);
    uint4 ra1 = *(const uint4*)(aptr + 8);
    uint4 rb0 = *(const uint4*)(bptr);
    uint4 rb1 = *(const uint4*)(bptr + 8);
    *(uint4*)&As[lrow * S1 + lkq]     = ra0;
    *(uint4*)&As[lrow * S1 + lkq + 8] = ra1;
    *(uint4*)&Bs[lrow * S1 + lkq]     = rb0;
    *(uint4*)&Bs[lrow * S1 + lkq + 8] = rb1;
    __syncthreads();

    for (int kt = 0; kt < FD; kt += 32) {
        bool more = (kt + 32 < FD);
        if (more) {
            ra0 = *(const uint4*)(aptr + kt + 32);
            ra1 = *(const uint4*)(aptr + kt + 40);
            rb0 = *(const uint4*)(bptr + kt + 32);
            rb1 = *(const uint4*)(bptr + kt + 40);
        }
        #pragma unroll
        for (int ks = 0; ks < 32; ks += 16) {
            unsigned bf[4][2];
            #pragma unroll
            for (int j = 0; j < 4; j++)
                ldsm_x2(bf[j], bBase + ((j * 8 * S1 + ks) << 1));
            #pragma unroll
            for (int i = 0; i < 4; i++) {
                unsigned af[4];
                ldsm_x4(af, aBase + ((i * 16 * S1 + ks) << 1));
                #pragma unroll
                for (int j = 0; j < 4; j++) mma_f16(acc[i][j], af, bf[j]);
            }
        }
        __syncthreads();
        if (more) {
            *(uint4*)&As[lrow * S1 + lkq]     = ra0;
            *(uint4*)&As[lrow * S1 + lkq + 8] = ra1;
            *(uint4*)&Bs[lrow * S1 + lkq]     = rb0;
            *(uint4*)&Bs[lrow * S1 + lkq + 8] = rb1;
            __syncthreads();
        }
    }

    // Epilogue: bias, write h (fp16), fused BN partials -> slotted atomics
    float s0[4] = {0.f,0.f,0.f,0.f}, q0[4] = {0.f,0.f,0.f,0.f};
    float s1[4] = {0.f,0.f,0.f,0.f}, q1[4] = {0.f,0.f,0.f,0.f};
    #pragma unroll
    for (int i = 0; i < 4; i++) {
        int r0 = m0 + wm + 16 * i + g;
        int r1 = r0 + 8;
        #pragma unroll
        for (int j = 0; j < 4; j++) {
            int lc = wn + 8 * j + 2 * t;
            float b0v = s_bias[lc], b1v = s_bias[lc + 1];
            float h00 = acc[i][j][0] + b0v, h01 = acc[i][j][1] + b1v;
            float h10 = acc[i][j][2] + b0v, h11 = acc[i][j][3] + b1v;
            if (r0 < NN) {
                *(__half2*)&g_hh[r0 * NH + n0 + lc] = __float22half2_rn(make_float2(h00, h01));
                s0[j] += h00; q0[j] = fmaf(h00, h00, q0[j]);
                s1[j] += h01; q1[j] = fmaf(h01, h01, q1[j]);
            }
            if (r1 < NN) {
                *(__half2*)&g_hh[r1 * NH + n0 + lc] = __float22half2_rn(make_float2(h10, h11));
                s0[j] += h10; q0[j] = fmaf(h10, h10, q0[j]);
                s1[j] += h11; q1[j] = fmaf(h11, h11, q1[j]);
            }
        }
    }
    #pragma unroll
    for (int j = 0; j < 4; j++) {
        #pragma unroll
        for (int off = 4; off < 32; off <<= 1) {
            s0[j] += __shfl_xor_sync(0xffffffff, s0[j], off);
            q0[j] += __shfl_xor_sync(0xffffffff, q0[j], off);
            s1[j] += __shfl_xor_sync(0xffffffff, s1[j], off);
            q1[j] += __shfl_xor_sync(0xffffffff, q1[j], off);
        }
    }
    if (lane < 4) {
        int slot = ((blockIdx.x ^ wid) & (NSLOT - 1)) * NH;
        #pragma unroll
        for (int j = 0; j < 4; j++) {
            int col = n0 + wn + 8 * j + 2 * lane;
            atomicAdd(&g_colsum[slot + col],     s0[j]);
            atomicAdd(&g_colsum[slot + col + 1], s1[j]);
            atomicAdd(&g_colsq[slot + col],      q0[j]);
            atomicAdd(&g_colsq[slot + col + 1],  q1[j]);
        }
    }
}

// ---------------- GEMM2 (fp16 MMA + ldmatrix): out = relu(h*sc+sh) @ W2^T + b2 ----------------
__global__ __launch_bounds__(256) void k_gemm2(const float* __restrict__ gamma,
                                               const float* __restrict__ beta,
                                               const float* __restrict__ b2,
                                               float* __restrict__ out) {
    __shared__ __half As[128 * S1];
    __shared__ __half Bs[64 * S1];
    __shared__ float s_scale[NH];
    __shared__ float s_shift[NH];
    __shared__ float s_b2[NC];
    const int tid = threadIdx.x;
    const int m0 = blockIdx.x * 128;
    const int wid = tid >> 5, lane = tid & 31;
    const int g = lane >> 2, t = lane & 3;
    const int wm = (wid & 3) * 32, wn = (wid >> 2) * 32;
    // BN finalize from slotted partials (redundant per block)
    for (int i = tid; i < NH; i += 256) {
        float s = 0.f, q = 0.f;
        #pragma unroll
        for (int r = 0; r < NSLOT; r++) { s += g_colsum[r * NH + i]; q += g_colsq[r * NH + i]; }
        float mean = s * (1.0f / NN);
        float var  = q * (1.0f / NN) - mean * mean;
        float sc = gamma[i] * rsqrtf(var + 1e-5f);
        s_scale[i] = sc;
        s_shift[i] = beta[i] - mean * sc;
    }
    if (tid < NC) s_b2[tid] = b2[tid];

    float acc[2][4][4];
    #pragma unroll
    for (int i = 0; i < 2; i++)
        #pragma unroll
        for (int j = 0; j < 4; j++)
            #pragma unroll
            for (int r = 0; r < 4; r++) acc[i][j][r] = 0.f;

    const unsigned asb = (unsigned)__cvta_generic_to_shared(As);
    const unsigned bsb = (unsigned)__cvta_generic_to_shared(Bs);
    const unsigned aBase = asb + (((wm + (lane & 15)) * S1 + (lane >> 4) * 8) << 1);
    const unsigned bBase = bsb + (((wn + (lane & 7)) * S1 + ((lane >> 3) & 1) * 8) << 1);

    const int lrow = tid >> 1, lkq = (tid & 1) * 16;
    const int brow = tid >> 2, bkq = (tid & 3) * 8;
    int gr = m0 + lrow; if (gr >= NN) gr = NN - 1;
    const __half* aptr = &g_hh[gr * NH + lkq];
    const __half* bptr = &g_w2h[brow * NH + bkq];

    uint4 ra0 = *(const uint4*)(aptr);
    uint4 ra1 = *(const uint4*)(aptr + 8);
    uint4 rb0 = *(const uint4*)(bptr);
    __syncthreads();   // s_scale/s_shift ready

    {
        unsigned res[8];
        const unsigned* vp = (const unsigned*)&ra0;
        #pragma unroll
        for (int p = 0; p < 4; p++) {
            int k = lkq + p * 2;
            float2 f = __half22float2(*(__half2*)&vp[p]);
            f.x = fmaxf(fmaf(f.x, s_scale[k],     s_shift[k]),     0.f);
            f.y = fmaxf(fmaf(f.y, s_scale[k + 1], s_shift[k + 1]), 0.f);
            __half2 h = __float22half2_rn(f);
            res[p] = *(unsigned*)&h;
        }
        const unsigned* wq = (const unsigned*)&ra1;
        #pragma unroll
        for (int p = 0; p < 4; p++) {
            int k = lkq + 8 + p * 2;
            float2 f = __half22float2(*(__half2*)&wq[p]);
            f.x = fmaxf(fmaf(f.x, s_scale[k],     s_shift[k]),     0.f);
            f.y = fmaxf(fmaf(f.y, s_scale[k + 1], s_shift[k + 1]), 0.f);
            __half2 h = __float22half2_rn(f);
            res[p + 4] = *(unsigned*)&h;
        }
        *(uint4*)&As[lrow * S1 + lkq]     = *(uint4*)&res[0];
        *(uint4*)&As[lrow * S1 + lkq + 8] = *(uint4*)&res[4];
        *(uint4*)&Bs[brow * S1 + bkq] = rb0;
    }
    __syncthreads();

    for (int kt = 0; kt < NH; kt += 32) {
        bool more = (kt + 32 < NH);
        if (more) {
            ra0 = *(const uint4*)(aptr + kt + 32);
            ra1 = *(const uint4*)(aptr + kt + 40);
            rb0 = *(const uint4*)(bptr + kt + 32);
        }
        #pragma unroll
        for (int ks = 0; ks < 32; ks += 16) {
            unsigned bf[4][2];
            #pragma unroll
            for (int j = 0; j < 4; j++)
                ldsm_x2(bf[j], bBase + ((j * 8 * S1 + ks) << 1));
            #pragma unroll
            for (int i = 0; i < 2; i++) {
                unsigned af[4];
                ldsm_x4(af, aBase + ((i * 16 * S1 + ks) << 1));
                #pragma unroll
                for (int j = 0; j < 4; j++) mma_f16(acc[i][j], af, bf[j]);
            }
        }
        __syncthreads();
        if (more) {
            int kb = kt + 32;
            unsigned res[8];
            const unsigned* vp = (const unsigned*)&ra0;
            #pragma unroll
            for (int p = 0; p < 4; p++) {
                int k = kb + lkq + p * 2;
                float2 f = __half22float2(*(__half2*)&vp[p]);
                f.x = fmaxf(fmaf(f.x, s_scale[k],     s_shift[k]),     0.f);
                f.y = fmaxf(fmaf(f.y, s_scale[k + 1], s_shift[k + 1]), 0.f);
                __half2 h = __float22half2_rn(f);
                res[p] = *(unsigned*)&h;
            }
            const unsigned* wq = (const unsigned*)&ra1;
            #pragma unroll
            for (int p = 0; p < 4; p++) {
                int k = kb + lkq + 8 + p * 2;
                float2 f = __half22float2(*(__half2*)&wq[p]);
                f.x = fmaxf(fmaf(f.x, s_scale[k],     s_shift[k]),     0.f);
                f.y = fmaxf(fmaf(f.y, s_scale[k + 1], s_shift[k + 1]), 0.f);
                __half2 h = __float22half2_rn(f);
                res[p + 4] = *(unsigned*)&h;
            }
            *(uint4*)&As[lrow * S1 + lkq]     = *(uint4*)&res[0];
            *(uint4*)&As[lrow * S1 + lkq + 8] = *(uint4*)&res[4];
            *(uint4*)&Bs[brow * S1 + bkq] = rb0;
            __syncthreads();
        }
    }
    #pragma unroll
    for (int i = 0; i < 2; i++) {
        int r0 = m0 + wm + 16 * i + g;
        int r1 = r0 + 8;
        #pragma unroll
        for (int j = 0; j < 4; j++) {
            int col = wn + 8 * j + 2 * t;
            float b0v = s_b2[col], b1v = s_b2[col + 1];
            if (r0 < NN)
                *(float2*)&out[r0 * NC + col] = make_float2(acc[i][j][0] + b0v, acc[i][j][1] + b1v);
            if (r1 < NN)
                *(float2*)&out[r1 * NC + col] = make_float2(acc[i][j][2] + b0v, acc[i][j][3] + b1v);
        }
    }
}

// ---------------- host launch ----------------
extern "C" void kernel_launch(void* const* d_in, const int* in_sizes, int n_in,
                              void* d_out, int out_size) {
    const float* feat   = (const float*)d_in[0];
    const int*   src    = (const int*)d_in[1];
    const int*   dst    = (const int*)d_in[2];
    const float* nrm    = (const float*)d_in[3];
    const float* fc1_w  = (const float*)d_in[4];
    const float* fc1_b  = (const float*)d_in[5];
    const float* gamma  = (const float*)d_in[6];
    const float* beta   = (const float*)d_in[7];
    const float* fc2_w  = (const float*)d_in[8];
    const float* fc2_b  = (const float*)d_in[9];
    float* out = (float*)d_out;

    k_cvthist<<<(NN * FD / 2 + 255) / 256, 256>>>(feat, fc1_w, fc2_w, dst);
    k_scan<<<SCAN_BLOCKS, 1024>>>();
    k_scatter<<<(NE / 4 + 255) / 256, 256>>>(src, dst, nrm);

    int prop_blocks = (NN * 32 + 255) / 256;
    k_prop<<<prop_blocks, 256>>>(0);   // 4th launch -> ncu capture window
    k_prop<<<prop_blocks, 256>>>(1);
    k_prop<<<prop_blocks, 256>>>(0);

    dim3 g1((NN + 127) / 128, NH / 128);
    k_gemm1<<<g1, 256>>>(fc1_b);
    k_gemm2<<<(NN + 127) / 128, 256>>>(gamma, beta, fc2_b, out);
}